// round 1
// baseline (speedup 1.0000x reference)
#include <cuda_runtime.h>

#define NN   100000
#define EE   3200000
#define HH   64
#define KDES 768
#define RNEG 0.01f
#define BNEPS 1e-5f

// ---------------- scratch (static __device__ globals; no allocation) ----------------
__device__ float4 g_xv[NN * 16];          // fused node features x [N,64] as float4
__device__ float4 g_Av[2][NN * 16];       // per-relation accumulators [N,64]
__device__ int    g_cnt[2][NN];           // per-relation in-degree counts
__device__ float  g_Wdes[KDES * HH];      // BN-folded, k-major
__device__ float  g_bdes[HH];
__device__ float  g_Wnum[5 * HH];
__device__ float  g_bnum[HH];
__device__ float  g_Wcat[6 * HH];
__device__ float  g_bcat[HH];
__device__ float  g_Wr[2][HH * HH];       // rgcn weights, k-major

__device__ __forceinline__ float leaky(float v) { return v > 0.f ? v : RNEG * v; }

// ---------------- prep: fold BN into linear weights, transpose to k-major ----------------
__global__ void prep_kernel(const float* __restrict__ desW, const float* __restrict__ desb,
                            const float* __restrict__ numW, const float* __restrict__ numb,
                            const float* __restrict__ catW, const float* __restrict__ catb,
                            const float* __restrict__ desg, const float* __restrict__ desbeta,
                            const float* __restrict__ desm, const float* __restrict__ desv,
                            const float* __restrict__ numg, const float* __restrict__ numbeta,
                            const float* __restrict__ numm, const float* __restrict__ numv,
                            const float* __restrict__ catg, const float* __restrict__ catbeta,
                            const float* __restrict__ catm, const float* __restrict__ catv,
                            const float* __restrict__ rgcnW)
{
    int idx = blockIdx.x * blockDim.x + threadIdx.x;
    if (idx < KDES * HH) {
        int k = idx >> 6, h = idx & 63;
        float s = desg[h] * rsqrtf(desv[h] + BNEPS);
        g_Wdes[k * HH + h] = desW[h * KDES + k] * s;
    }
    if (idx < 5 * HH) {
        int k = idx >> 6, h = idx & 63;
        float s = numg[h] * rsqrtf(numv[h] + BNEPS);
        g_Wnum[k * HH + h] = numW[h * 5 + k] * s;
    }
    if (idx < 6 * HH) {
        int k = idx >> 6, h = idx & 63;
        float s = catg[h] * rsqrtf(catv[h] + BNEPS);
        g_Wcat[k * HH + h] = catW[h * 6 + k] * s;
    }
    if (idx < 2 * HH * HH) {
        int r = idx >> 12;
        int rem = idx & 4095;
        int h = rem >> 6, k = rem & 63;
        g_Wr[r][k * HH + h] = rgcnW[r * HH * HH + h * HH + k];
    }
    if (idx < HH) {
        int h = idx;
        float sd = desg[h] * rsqrtf(desv[h] + BNEPS);
        g_bdes[h] = (desb[h] - desm[h]) * sd + desbeta[h];
        float sn = numg[h] * rsqrtf(numv[h] + BNEPS);
        g_bnum[h] = (numb[h] - numm[h]) * sn + numbeta[h];
        float sc = catg[h] * rsqrtf(catv[h] + BNEPS);
        g_bcat[h] = (catb[h] - catm[h]) * sc + catbeta[h];
    }
}

// ---------------- zero accumulators + counts ----------------
__global__ void zero_kernel()
{
    int idx = blockIdx.x * blockDim.x + threadIdx.x;
    const int NV = 2 * NN * 16;  // float4 slots
    if (idx < NV) {
        ((float4*)g_Av)[idx] = make_float4(0.f, 0.f, 0.f, 0.f);
    } else {
        int j = idx - NV;
        if (j < 2 * NN) ((int*)g_cnt)[j] = 0;
    }
}

// ---------------- fused feature kernel: x = leaky(BN(des@W)) + leaky(BN(num@W)) + leaky(BN(cat@W)) ----------------
// Tiled fp32 GEMM: BM=128, BN=64 (full), BK=16, 256 threads, 8x4 microtile/thread.
__global__ void feat_kernel(const float* __restrict__ des, const float* __restrict__ num,
                            const float* __restrict__ cat)
{
    __shared__ float As[16][132];   // [k][row], padded
    __shared__ float Bs[16][64];    // [k][col]
    int tid = threadIdx.x;
    int tx = tid & 15;       // col group: cols tx*4..tx*4+3
    int ty = tid >> 4;       // row group: rows ty*8..ty*8+7
    int row0 = blockIdx.x * 128;
    int c0 = tx * 4;
    int rl = ty * 8;

    float acc[8][4];
#pragma unroll
    for (int j = 0; j < 8; j++)
#pragma unroll
        for (int i = 0; i < 4; i++) acc[j][i] = 0.f;

    for (int kk = 0; kk < KDES; kk += 16) {
        // load A tile (128 rows x 16 k), transposed into As[k][row]
#pragma unroll
        for (int t = 0; t < 2; t++) {
            int f = tid + t * 256;       // float4 slot 0..511
            int r = f >> 2;              // row within tile
            int kq = f & 3;              // which float4 along k
            float4 v = make_float4(0.f, 0.f, 0.f, 0.f);
            int grow = row0 + r;
            if (grow < NN) v = *(const float4*)&des[(size_t)grow * KDES + kk + kq * 4];
            As[kq * 4 + 0][r] = v.x;
            As[kq * 4 + 1][r] = v.y;
            As[kq * 4 + 2][r] = v.z;
            As[kq * 4 + 3][r] = v.w;
        }
        // load B tile (16 k x 64 cols)
        {
            int kb = tid >> 4, cb = (tid & 15) * 4;
            *(float4*)&Bs[kb][cb] = *(const float4*)&g_Wdes[(kk + kb) * HH + cb];
        }
        __syncthreads();
#pragma unroll
        for (int k = 0; k < 16; k++) {
            float4 b4 = *(const float4*)&Bs[k][c0];
            float4 a0 = *(const float4*)&As[k][rl];
            float4 a1 = *(const float4*)&As[k][rl + 4];
            float a[8] = {a0.x, a0.y, a0.z, a0.w, a1.x, a1.y, a1.z, a1.w};
            float b[4] = {b4.x, b4.y, b4.z, b4.w};
#pragma unroll
            for (int j = 0; j < 8; j++)
#pragma unroll
                for (int i = 0; i < 4; i++)
                    acc[j][i] += a[j] * b[i];
        }
        __syncthreads();
    }

    // epilogue: bias + leaky per branch, add tiny num/cat branches, store x
#pragma unroll
    for (int j = 0; j < 8; j++) {
        int grow = row0 + rl + j;
        if (grow < NN) {
            float nbuf[5], cbuf[6];
#pragma unroll
            for (int k = 0; k < 5; k++) nbuf[k] = num[grow * 5 + k];
#pragma unroll
            for (int k = 0; k < 6; k++) cbuf[k] = cat[grow * 6 + k];
            float res[4];
#pragma unroll
            for (int i = 0; i < 4; i++) {
                int c = c0 + i;
                float vd = leaky(acc[j][i] + g_bdes[c]);
                float vn = g_bnum[c];
#pragma unroll
                for (int k = 0; k < 5; k++) vn += nbuf[k] * g_Wnum[k * HH + c];
                vn = leaky(vn);
                float vc = g_bcat[c];
#pragma unroll
                for (int k = 0; k < 6; k++) vc += cbuf[k] * g_Wcat[k * HH + c];
                vc = leaky(vc);
                res[i] = vd + vn + vc;
            }
            g_xv[grow * 16 + tx] = make_float4(res[0], res[1], res[2], res[3]);
        }
    }
}

// ---------------- scatter: per edge, A[type][dst] += x[src], cnt[type][dst] += 1 ----------------
// 16 lanes per edge, float4 per lane, vectorized global reductions.
__global__ void scatter_kernel(const int* __restrict__ ei, const int* __restrict__ et)
{
    int gid = blockIdx.x * 256 + threadIdx.x;   // up to 51.2M < 2^31
    int e = gid >> 4;
    if (e >= EE) return;
    int lane = gid & 15;
    int src = ei[e];
    int dst = ei[EE + e];
    int r = et[e];
    float4 v = g_xv[src * 16 + lane];
    float* addr = (float*)&g_Av[r][dst * 16 + lane];
    asm volatile("red.global.add.v4.f32 [%0], {%1, %2, %3, %4};"
                 :: "l"(addr), "f"(v.x), "f"(v.y), "f"(v.z), "f"(v.w)
                 : "memory");
    if (lane == 0) atomicAdd(&g_cnt[r][dst], 1);
}

// ---------------- finalize: mean, RGCN weight apply, leaky, classifier ----------------
__global__ void final_kernel(const float* __restrict__ W1, const float* __restrict__ b1,
                             const float* __restrict__ W2, const float* __restrict__ b2,
                             float* __restrict__ out)
{
    __shared__ float y0[64], y1[64], z[64], h1[32];
    int i = blockIdx.x;
    int t = threadIdx.x;
    float inv0 = 1.f / (float)max(g_cnt[0][i], 1);
    float inv1 = 1.f / (float)max(g_cnt[1][i], 1);
    const float* A0 = (const float*)&g_Av[0][i * 16];
    const float* A1 = (const float*)&g_Av[1][i * 16];
    y0[t] = A0[t] * inv0;
    y1[t] = A1[t] * inv1;
    __syncthreads();
    float acc = 0.f;
#pragma unroll
    for (int k = 0; k < 64; k++) {
        acc += y0[k] * g_Wr[0][k * HH + t];
        acc += y1[k] * g_Wr[1][k * HH + t];
    }
    z[t] = leaky(acc * 0.5f);
    __syncthreads();
    if (t < 32) {
        float a = b1[t];
#pragma unroll
        for (int k = 0; k < 64; k++) a += z[k] * W1[t * 64 + k];
        h1[t] = leaky(a);
    }
    __syncthreads();
    if (t < 2) {
        float a = b2[t];
#pragma unroll
        for (int j = 0; j < 32; j++) a += h1[j] * W2[t * 32 + j];
        out[i * 2 + t] = a;
    }
}

// ---------------- launch ----------------
extern "C" void kernel_launch(void* const* d_in, const int* in_sizes, int n_in,
                              void* d_out, int out_size)
{
    const float* des     = (const float*)d_in[0];
    const float* num     = (const float*)d_in[1];
    const float* cat     = (const float*)d_in[2];
    const int*   ei      = (const int*)d_in[3];
    const int*   et      = (const int*)d_in[4];
    const float* desW    = (const float*)d_in[5];
    const float* desb    = (const float*)d_in[6];
    const float* numW    = (const float*)d_in[7];
    const float* numb    = (const float*)d_in[8];
    const float* catW    = (const float*)d_in[9];
    const float* catb    = (const float*)d_in[10];
    const float* desg    = (const float*)d_in[11];
    const float* desbeta = (const float*)d_in[12];
    const float* desm    = (const float*)d_in[13];
    const float* desv    = (const float*)d_in[14];
    const float* numg    = (const float*)d_in[15];
    const float* numbeta = (const float*)d_in[16];
    const float* numm    = (const float*)d_in[17];
    const float* numv    = (const float*)d_in[18];
    const float* catg    = (const float*)d_in[19];
    const float* catbeta = (const float*)d_in[20];
    const float* catm    = (const float*)d_in[21];
    const float* catv    = (const float*)d_in[22];
    const float* rgcnW   = (const float*)d_in[23];
    const float* clsW1   = (const float*)d_in[24];
    const float* clsb1   = (const float*)d_in[25];
    const float* clsW2   = (const float*)d_in[26];
    const float* clsb2   = (const float*)d_in[27];
    float* out = (float*)d_out;

    prep_kernel<<<(KDES * HH + 255) / 256, 256>>>(
        desW, desb, numW, numb, catW, catb,
        desg, desbeta, desm, desv,
        numg, numbeta, numm, numv,
        catg, catbeta, catm, catv,
        rgcnW);

    zero_kernel<<<(2 * NN * 16 + 2 * NN + 255) / 256, 256>>>();

    feat_kernel<<<(NN + 127) / 128, 256>>>(des, num, cat);

    scatter_kernel<<<(EE * 16) / 256, 256>>>(ei, et);

    final_kernel<<<NN, 64>>>(clsW1, clsb1, clsW2, clsb2, out);
}

// round 2
// speedup vs baseline: 2.2423x; 2.2423x over previous
#include <cuda_runtime.h>

#define NN   100000
#define EE   3200000
#define HH   64
#define KDES 768
#define RNEG 0.01f
#define BNEPS 1e-5f

typedef unsigned long long ull;

// ---------------- scratch (static __device__ globals; no allocation) ----------------
__device__ float4 g_xv[NN * 16];          // fused node features x [N,64] as float4
__device__ float4 g_Av[2][NN * 16];       // per-relation accumulators [N,64]
__device__ int    g_cnt[2][NN];           // per-relation in-degree counts
__device__ float  g_Wdes[KDES * HH];      // BN-folded, k-major
__device__ float  g_bdes[HH];
__device__ float  g_Wnum[5 * HH];
__device__ float  g_bnum[HH];
__device__ float  g_Wcat[6 * HH];
__device__ float  g_bcat[HH];
__device__ float  g_Wr[2][HH * HH];       // rgcn weights, k-major

__device__ __forceinline__ float leaky(float v) { return v > 0.f ? v : RNEG * v; }

// packed f32x2 helpers
__device__ __forceinline__ void fma2(ull& d, ull a, ull b) {
    asm("fma.rn.f32x2 %0, %1, %2, %0;" : "+l"(d) : "l"(a), "l"(b));
}
__device__ __forceinline__ ull dupf(float x) {
    ull r; asm("mov.b64 %0, {%1, %1};" : "=l"(r) : "f"(x)); return r;
}
__device__ __forceinline__ float2 unpk(ull v) {
    float2 r; asm("mov.b64 {%0, %1}, %2;" : "=f"(r.x), "=f"(r.y) : "l"(v)); return r;
}

// ---------------- prep: fold BN into linear weights, transpose to k-major ----------------
__global__ void prep_kernel(const float* __restrict__ desW, const float* __restrict__ desb,
                            const float* __restrict__ numW, const float* __restrict__ numb,
                            const float* __restrict__ catW, const float* __restrict__ catb,
                            const float* __restrict__ desg, const float* __restrict__ desbeta,
                            const float* __restrict__ desm, const float* __restrict__ desv,
                            const float* __restrict__ numg, const float* __restrict__ numbeta,
                            const float* __restrict__ numm, const float* __restrict__ numv,
                            const float* __restrict__ catg, const float* __restrict__ catbeta,
                            const float* __restrict__ catm, const float* __restrict__ catv,
                            const float* __restrict__ rgcnW)
{
    int idx = blockIdx.x * blockDim.x + threadIdx.x;
    if (idx < KDES * HH) {
        int k = idx >> 6, h = idx & 63;
        float s = desg[h] * rsqrtf(desv[h] + BNEPS);
        g_Wdes[k * HH + h] = desW[h * KDES + k] * s;
    }
    if (idx < 5 * HH) {
        int k = idx >> 6, h = idx & 63;
        float s = numg[h] * rsqrtf(numv[h] + BNEPS);
        g_Wnum[k * HH + h] = numW[h * 5 + k] * s;
    }
    if (idx < 6 * HH) {
        int k = idx >> 6, h = idx & 63;
        float s = catg[h] * rsqrtf(catv[h] + BNEPS);
        g_Wcat[k * HH + h] = catW[h * 6 + k] * s;
    }
    if (idx < 2 * HH * HH) {
        int r = idx >> 12;
        int rem = idx & 4095;
        int h = rem >> 6, k = rem & 63;
        g_Wr[r][k * HH + h] = rgcnW[r * HH * HH + h * HH + k];
    }
    if (idx < HH) {
        int h = idx;
        float sd = desg[h] * rsqrtf(desv[h] + BNEPS);
        g_bdes[h] = (desb[h] - desm[h]) * sd + desbeta[h];
        float sn = numg[h] * rsqrtf(numv[h] + BNEPS);
        g_bnum[h] = (numb[h] - numm[h]) * sn + numbeta[h];
        float sc = catg[h] * rsqrtf(catv[h] + BNEPS);
        g_bcat[h] = (catb[h] - catm[h]) * sc + catbeta[h];
    }
}

// ---------------- zero accumulators + counts ----------------
__global__ void zero_kernel()
{
    int idx = blockIdx.x * blockDim.x + threadIdx.x;
    const int NV = 2 * NN * 16;  // float4 slots
    if (idx < NV) {
        ((float4*)g_Av)[idx] = make_float4(0.f, 0.f, 0.f, 0.f);
    } else {
        int j = idx - NV;
        if (j < 2 * NN) ((int*)g_cnt)[j] = 0;
    }
}

// ---------------- fused feature kernel (f32x2 packed FFMA + double buffering) ----------------
// BM=128, BN=64 (full), BK=16, 256 threads, 8x4 microtile/thread (4 row-pairs x 4 cols).
__global__ __launch_bounds__(256) void feat_kernel(const float* __restrict__ des,
                                                   const float* __restrict__ num,
                                                   const float* __restrict__ cat)
{
    __shared__ float As[2][16][132];   // [buf][k][row], padded
    __shared__ float Bs[2][16][64];    // [buf][k][col]
    int tid = threadIdx.x;
    int tx = tid & 15;       // col group: cols tx*4..tx*4+3
    int ty = tid >> 4;       // row group: rows ty*8..ty*8+7
    int row0 = blockIdx.x * 128;
    int c0 = tx * 4;
    int rl = ty * 8;

    // global-load assignments
    int r0 = tid >> 2, kq0 = tid & 3;          // A float4 slot #tid
    int r1 = (tid + 256) >> 2;                 // A float4 slot #tid+256 (same kq)
    int kb = tid >> 4, cb = (tid & 15) * 4;    // B slot

    ull acc2[4][4];
#pragma unroll
    for (int j = 0; j < 4; j++)
#pragma unroll
        for (int i = 0; i < 4; i++) acc2[j][i] = 0ull;

    float4 pA0, pA1, pB;
    auto gload = [&](int kk) {
        int g0 = row0 + r0, g1 = row0 + r1;
        pA0 = (g0 < NN) ? *(const float4*)&des[(size_t)g0 * KDES + kk + kq0 * 4]
                        : make_float4(0.f, 0.f, 0.f, 0.f);
        pA1 = (g1 < NN) ? *(const float4*)&des[(size_t)g1 * KDES + kk + kq0 * 4]
                        : make_float4(0.f, 0.f, 0.f, 0.f);
        pB  = *(const float4*)&g_Wdes[(kk + kb) * HH + cb];
    };
    auto sstore = [&](int buf) {
        As[buf][kq0 * 4 + 0][r0] = pA0.x;
        As[buf][kq0 * 4 + 1][r0] = pA0.y;
        As[buf][kq0 * 4 + 2][r0] = pA0.z;
        As[buf][kq0 * 4 + 3][r0] = pA0.w;
        As[buf][kq0 * 4 + 0][r1] = pA1.x;
        As[buf][kq0 * 4 + 1][r1] = pA1.y;
        As[buf][kq0 * 4 + 2][r1] = pA1.z;
        As[buf][kq0 * 4 + 3][r1] = pA1.w;
        *(float4*)&Bs[buf][kb][cb] = pB;
    };

    gload(0);
    sstore(0);
    __syncthreads();

    const int T = KDES / 16;   // 48
    for (int t = 0; t < T; t++) {
        int buf = t & 1;
        bool more = (t + 1 < T);
        if (more) gload((t + 1) * 16);
#pragma unroll
        for (int k = 0; k < 16; k++) {
            float4 b4 = *(const float4*)&Bs[buf][k][c0];
            ull bd0 = dupf(b4.x), bd1 = dupf(b4.y), bd2 = dupf(b4.z), bd3 = dupf(b4.w);
            ulonglong2 a01 = *(const ulonglong2*)&As[buf][k][rl];
            ulonglong2 a23 = *(const ulonglong2*)&As[buf][k][rl + 4];
            fma2(acc2[0][0], a01.x, bd0); fma2(acc2[0][1], a01.x, bd1);
            fma2(acc2[0][2], a01.x, bd2); fma2(acc2[0][3], a01.x, bd3);
            fma2(acc2[1][0], a01.y, bd0); fma2(acc2[1][1], a01.y, bd1);
            fma2(acc2[1][2], a01.y, bd2); fma2(acc2[1][3], a01.y, bd3);
            fma2(acc2[2][0], a23.x, bd0); fma2(acc2[2][1], a23.x, bd1);
            fma2(acc2[2][2], a23.x, bd2); fma2(acc2[2][3], a23.x, bd3);
            fma2(acc2[3][0], a23.y, bd0); fma2(acc2[3][1], a23.y, bd1);
            fma2(acc2[3][2], a23.y, bd2); fma2(acc2[3][3], a23.y, bd3);
        }
        if (more) sstore((t + 1) & 1);
        __syncthreads();
    }

    // epilogue: bias + leaky per branch, add tiny num/cat branches, store x
#pragma unroll
    for (int j = 0; j < 8; j++) {
        int grow = row0 + rl + j;
        if (grow < NN) {
            int jp = j >> 1, hi = j & 1;
            float nbuf[5], cbuf[6];
#pragma unroll
            for (int k = 0; k < 5; k++) nbuf[k] = num[grow * 5 + k];
#pragma unroll
            for (int k = 0; k < 6; k++) cbuf[k] = cat[grow * 6 + k];
            float res[4];
#pragma unroll
            for (int i = 0; i < 4; i++) {
                float2 u = unpk(acc2[jp][i]);
                float av = hi ? u.y : u.x;
                int c = c0 + i;
                float vd = leaky(av + g_bdes[c]);
                float vn = g_bnum[c];
#pragma unroll
                for (int k = 0; k < 5; k++) vn += nbuf[k] * g_Wnum[k * HH + c];
                vn = leaky(vn);
                float vc = g_bcat[c];
#pragma unroll
                for (int k = 0; k < 6; k++) vc += cbuf[k] * g_Wcat[k * HH + c];
                vc = leaky(vc);
                res[i] = vd + vn + vc;
            }
            g_xv[grow * 16 + tx] = make_float4(res[0], res[1], res[2], res[3]);
        }
    }
}

// ---------------- scatter: per edge, A[type][dst] += x[src], cnt[type][dst] += 1 ----------------
__global__ void scatter_kernel(const int* __restrict__ ei, const int* __restrict__ et)
{
    int gid = blockIdx.x * 256 + threadIdx.x;
    int e = gid >> 4;
    if (e >= EE) return;
    int lane = gid & 15;
    int src = ei[e];
    int dst = ei[EE + e];
    int r = et[e];
    float4 v = g_xv[src * 16 + lane];
    float* addr = (float*)&g_Av[r][dst * 16 + lane];
    asm volatile("red.global.add.v4.f32 [%0], {%1, %2, %3, %4};"
                 :: "l"(addr), "f"(v.x), "f"(v.y), "f"(v.z), "f"(v.w)
                 : "memory");
    if (lane == 0) atomicAdd(&g_cnt[r][dst], 1);
}

// ---------------- finalize: tiled, weights staged in smem ----------------
// Block = 256 threads (8 warps), covers 128 nodes (16 per warp).
__global__ __launch_bounds__(256) void final_kernel(const float* __restrict__ W1,
                                                    const float* __restrict__ b1,
                                                    const float* __restrict__ W2,
                                                    const float* __restrict__ b2,
                                                    float* __restrict__ out)
{
    __shared__ float2 W0p[64 * 32];   // W0p[k*32+l] = (Wr0[k][l], Wr0[k][l+32])
    __shared__ float2 W1p[64 * 32];
    __shared__ float  C1t[64 * 32];   // C1t[k*32+o] = clsW1[o][k]
    __shared__ float  C2s[64];
    __shared__ float  ys0[8][64];
    __shared__ float  ys1[8][64];
    __shared__ float  zs[8][64];

    int tid = threadIdx.x, w = tid >> 5, lane = tid & 31;

    for (int idx = tid; idx < 2048; idx += 256) {
        int k = idx >> 5, l = idx & 31;
        W0p[idx] = make_float2(g_Wr[0][k * HH + l], g_Wr[0][k * HH + l + 32]);
        W1p[idx] = make_float2(g_Wr[1][k * HH + l], g_Wr[1][k * HH + l + 32]);
        C1t[idx] = W1[l * 64 + k];
    }
    if (tid < 64) C2s[tid] = W2[tid];
    __syncthreads();

    const ull* W0u = (const ull*)W0p;
    const ull* W1u = (const ull*)W1p;
    float b1v = b1[lane];
    float b20 = b2[0], b21 = b2[1];

    int base = blockIdx.x * 128 + w * 16;
    for (int nt = 0; nt < 16; nt++) {
        int node = base + nt;
        if (node >= NN) break;
        float inv0 = 1.f / (float)max(g_cnt[0][node], 1);
        float inv1 = 1.f / (float)max(g_cnt[1][node], 1);
        const float2* A0 = (const float2*)&g_Av[0][node * 16];
        const float2* A1 = (const float2*)&g_Av[1][node * 16];
        float2 p0 = A0[lane], p1 = A1[lane];
        ((float2*)ys0[w])[lane] = make_float2(p0.x * inv0, p0.y * inv0);
        ((float2*)ys1[w])[lane] = make_float2(p1.x * inv1, p1.y * inv1);
        __syncwarp();

        ull acc = 0ull;
#pragma unroll 16
        for (int k = 0; k < 64; k++) {
            ull a0 = dupf(ys0[w][k]);
            ull a1 = dupf(ys1[w][k]);
            fma2(acc, a0, W0u[k * 32 + lane]);
            fma2(acc, a1, W1u[k * 32 + lane]);
        }
        float2 zz = unpk(acc);
        zs[w][lane]      = leaky(zz.x * 0.5f);
        zs[w][lane + 32] = leaky(zz.y * 0.5f);
        __syncwarp();

        float h = b1v;
#pragma unroll 16
        for (int k = 0; k < 64; k++) h += zs[w][k] * C1t[k * 32 + lane];
        h = leaky(h);

        float q0 = h * C2s[lane], q1 = h * C2s[32 + lane];
#pragma unroll
        for (int off = 16; off; off >>= 1) {
            q0 += __shfl_down_sync(0xffffffffu, q0, off);
            q1 += __shfl_down_sync(0xffffffffu, q1, off);
        }
        if (lane == 0) {
            out[node * 2 + 0] = q0 + b20;
            out[node * 2 + 1] = q1 + b21;
        }
    }
}

// ---------------- launch ----------------
extern "C" void kernel_launch(void* const* d_in, const int* in_sizes, int n_in,
                              void* d_out, int out_size)
{
    const float* des     = (const float*)d_in[0];
    const float* num     = (const float*)d_in[1];
    const float* cat     = (const float*)d_in[2];
    const int*   ei      = (const int*)d_in[3];
    const int*   et      = (const int*)d_in[4];
    const float* desW    = (const float*)d_in[5];
    const float* desb    = (const float*)d_in[6];
    const float* numW    = (const float*)d_in[7];
    const float* numb    = (const float*)d_in[8];
    const float* catW    = (const float*)d_in[9];
    const float* catb    = (const float*)d_in[10];
    const float* desg    = (const float*)d_in[11];
    const float* desbeta = (const float*)d_in[12];
    const float* desm    = (const float*)d_in[13];
    const float* desv    = (const float*)d_in[14];
    const float* numg    = (const float*)d_in[15];
    const float* numbeta = (const float*)d_in[16];
    const float* numm    = (const float*)d_in[17];
    const float* numv    = (const float*)d_in[18];
    const float* catg    = (const float*)d_in[19];
    const float* catbeta = (const float*)d_in[20];
    const float* catm    = (const float*)d_in[21];
    const float* catv    = (const float*)d_in[22];
    const float* rgcnW   = (const float*)d_in[23];
    const float* clsW1   = (const float*)d_in[24];
    const float* clsb1   = (const float*)d_in[25];
    const float* clsW2   = (const float*)d_in[26];
    const float* clsb2   = (const float*)d_in[27];
    float* out = (float*)d_out;

    prep_kernel<<<(KDES * HH + 255) / 256, 256>>>(
        desW, desb, numW, numb, catW, catb,
        desg, desbeta, desm, desv,
        numg, numbeta, numm, numv,
        catg, catbeta, catm, catv,
        rgcnW);

    zero_kernel<<<(2 * NN * 16 + 2 * NN + 255) / 256, 256>>>();

    feat_kernel<<<(NN + 127) / 128, 256>>>(des, num, cat);

    scatter_kernel<<<(EE * 16) / 256, 256>>>(ei, et);

    final_kernel<<<(NN + 127) / 128, 256>>>(clsW1, clsb1, clsW2, clsb2, out);
}

// round 3
// speedup vs baseline: 2.8741x; 1.2818x over previous
#include <cuda_runtime.h>

#define NN   100000
#define EE   3200000
#define HH   64
#define KDES 768
#define RNEG 0.01f
#define BNEPS 1e-5f

typedef unsigned long long ull;

// ---------------- scratch (static __device__ globals; no allocation) ----------------
__device__ float4 g_xv[NN * 16];          // node features x [N,64]; later reused for Z
__device__ float4 g_Av[2][NN * 16];       // per-relation raw sums [N,64]
__device__ int    g_cnt[2][NN];           // per-relation in-degree counts
__device__ float  g_Wdes[KDES * HH];      // BN-folded, k-major
__device__ float  g_bdes[HH];
__device__ float  g_Wnum[5 * HH];
__device__ float  g_bnum[HH];
__device__ float  g_Wcat[6 * HH];
__device__ float  g_bcat[HH];
__device__ float  g_Wr[2][HH * HH];       // rgcn weights, k-major

__device__ __forceinline__ float leaky(float v) { return v > 0.f ? v : RNEG * v; }

// packed f32x2 helpers
__device__ __forceinline__ void fma2(ull& d, ull a, ull b) {
    asm("fma.rn.f32x2 %0, %1, %2, %0;" : "+l"(d) : "l"(a), "l"(b));
}
__device__ __forceinline__ ull dupf(float x) {
    ull r; asm("mov.b64 %0, {%1, %1};" : "=l"(r) : "f"(x)); return r;
}
__device__ __forceinline__ ull pk2(float a, float b) {
    ull r; asm("mov.b64 %0, {%1, %2};" : "=l"(r) : "f"(a), "f"(b)); return r;
}
__device__ __forceinline__ float2 unpk(ull v) {
    float2 r; asm("mov.b64 {%0, %1}, %2;" : "=f"(r.x), "=f"(r.y) : "l"(v)); return r;
}

// ---------------- prep: fold BN into linear weights, transpose to k-major ----------------
__global__ void prep_kernel(const float* __restrict__ desW, const float* __restrict__ desb,
                            const float* __restrict__ numW, const float* __restrict__ numb,
                            const float* __restrict__ catW, const float* __restrict__ catb,
                            const float* __restrict__ desg, const float* __restrict__ desbeta,
                            const float* __restrict__ desm, const float* __restrict__ desv,
                            const float* __restrict__ numg, const float* __restrict__ numbeta,
                            const float* __restrict__ numm, const float* __restrict__ numv,
                            const float* __restrict__ catg, const float* __restrict__ catbeta,
                            const float* __restrict__ catm, const float* __restrict__ catv,
                            const float* __restrict__ rgcnW)
{
    int idx = blockIdx.x * blockDim.x + threadIdx.x;
    if (idx < KDES * HH) {
        int k = idx >> 6, h = idx & 63;
        float s = desg[h] * rsqrtf(desv[h] + BNEPS);
        g_Wdes[k * HH + h] = desW[h * KDES + k] * s;
    }
    if (idx < 5 * HH) {
        int k = idx >> 6, h = idx & 63;
        float s = numg[h] * rsqrtf(numv[h] + BNEPS);
        g_Wnum[k * HH + h] = numW[h * 5 + k] * s;
    }
    if (idx < 6 * HH) {
        int k = idx >> 6, h = idx & 63;
        float s = catg[h] * rsqrtf(catv[h] + BNEPS);
        g_Wcat[k * HH + h] = catW[h * 6 + k] * s;
    }
    if (idx < 2 * HH * HH) {
        int r = idx >> 12;
        int rem = idx & 4095;
        int h = rem >> 6, k = rem & 63;
        g_Wr[r][k * HH + h] = rgcnW[r * HH * HH + h * HH + k];
    }
    if (idx < HH) {
        int h = idx;
        float sd = desg[h] * rsqrtf(desv[h] + BNEPS);
        g_bdes[h] = (desb[h] - desm[h]) * sd + desbeta[h];
        float sn = numg[h] * rsqrtf(numv[h] + BNEPS);
        g_bnum[h] = (numb[h] - numm[h]) * sn + numbeta[h];
        float sc = catg[h] * rsqrtf(catv[h] + BNEPS);
        g_bcat[h] = (catb[h] - catm[h]) * sc + catbeta[h];
    }
}

// ---------------- zero accumulators + counts ----------------
__global__ void zero_kernel()
{
    int idx = blockIdx.x * blockDim.x + threadIdx.x;
    const int NV = 2 * NN * 16;  // float4 slots
    if (idx < NV) {
        ((float4*)g_Av)[idx] = make_float4(0.f, 0.f, 0.f, 0.f);
    } else {
        int j = idx - NV;
        if (j < 2 * NN) ((int*)g_cnt)[j] = 0;
    }
}

// ---------------- fused feature kernel (f32x2 packed FFMA + double buffering) ----------------
__global__ __launch_bounds__(256) void feat_kernel(const float* __restrict__ des,
                                                   const float* __restrict__ num,
                                                   const float* __restrict__ cat)
{
    __shared__ float As[2][16][132];   // [buf][k][row], padded
    __shared__ float Bs[2][16][64];    // [buf][k][col]
    int tid = threadIdx.x;
    int tx = tid & 15;
    int ty = tid >> 4;
    int row0 = blockIdx.x * 128;
    int c0 = tx * 4;
    int rl = ty * 8;

    int r0 = tid >> 2, kq0 = tid & 3;
    int r1 = (tid + 256) >> 2;
    int kb = tid >> 4, cb = (tid & 15) * 4;

    ull acc2[4][4];
#pragma unroll
    for (int j = 0; j < 4; j++)
#pragma unroll
        for (int i = 0; i < 4; i++) acc2[j][i] = 0ull;

    float4 pA0, pA1, pB;
    auto gload = [&](int kk) {
        int g0 = row0 + r0, g1 = row0 + r1;
        pA0 = (g0 < NN) ? *(const float4*)&des[(size_t)g0 * KDES + kk + kq0 * 4]
                        : make_float4(0.f, 0.f, 0.f, 0.f);
        pA1 = (g1 < NN) ? *(const float4*)&des[(size_t)g1 * KDES + kk + kq0 * 4]
                        : make_float4(0.f, 0.f, 0.f, 0.f);
        pB  = *(const float4*)&g_Wdes[(kk + kb) * HH + cb];
    };
    auto sstore = [&](int buf) {
        As[buf][kq0 * 4 + 0][r0] = pA0.x;
        As[buf][kq0 * 4 + 1][r0] = pA0.y;
        As[buf][kq0 * 4 + 2][r0] = pA0.z;
        As[buf][kq0 * 4 + 3][r0] = pA0.w;
        As[buf][kq0 * 4 + 0][r1] = pA1.x;
        As[buf][kq0 * 4 + 1][r1] = pA1.y;
        As[buf][kq0 * 4 + 2][r1] = pA1.z;
        As[buf][kq0 * 4 + 3][r1] = pA1.w;
        *(float4*)&Bs[buf][kb][cb] = pB;
    };

    gload(0);
    sstore(0);
    __syncthreads();

    const int T = KDES / 16;   // 48
    for (int t = 0; t < T; t++) {
        int buf = t & 1;
        bool more = (t + 1 < T);
        if (more) gload((t + 1) * 16);
#pragma unroll
        for (int k = 0; k < 16; k++) {
            float4 b4 = *(const float4*)&Bs[buf][k][c0];
            ull bd0 = dupf(b4.x), bd1 = dupf(b4.y), bd2 = dupf(b4.z), bd3 = dupf(b4.w);
            ulonglong2 a01 = *(const ulonglong2*)&As[buf][k][rl];
            ulonglong2 a23 = *(const ulonglong2*)&As[buf][k][rl + 4];
            fma2(acc2[0][0], a01.x, bd0); fma2(acc2[0][1], a01.x, bd1);
            fma2(acc2[0][2], a01.x, bd2); fma2(acc2[0][3], a01.x, bd3);
            fma2(acc2[1][0], a01.y, bd0); fma2(acc2[1][1], a01.y, bd1);
            fma2(acc2[1][2], a01.y, bd2); fma2(acc2[1][3], a01.y, bd3);
            fma2(acc2[2][0], a23.x, bd0); fma2(acc2[2][1], a23.x, bd1);
            fma2(acc2[2][2], a23.x, bd2); fma2(acc2[2][3], a23.x, bd3);
            fma2(acc2[3][0], a23.y, bd0); fma2(acc2[3][1], a23.y, bd1);
            fma2(acc2[3][2], a23.y, bd2); fma2(acc2[3][3], a23.y, bd3);
        }
        if (more) sstore((t + 1) & 1);
        __syncthreads();
    }

#pragma unroll
    for (int j = 0; j < 8; j++) {
        int grow = row0 + rl + j;
        if (grow < NN) {
            int jp = j >> 1, hi = j & 1;
            float nbuf[5], cbuf[6];
#pragma unroll
            for (int k = 0; k < 5; k++) nbuf[k] = num[grow * 5 + k];
#pragma unroll
            for (int k = 0; k < 6; k++) cbuf[k] = cat[grow * 6 + k];
            float res[4];
#pragma unroll
            for (int i = 0; i < 4; i++) {
                float2 u = unpk(acc2[jp][i]);
                float av = hi ? u.y : u.x;
                int c = c0 + i;
                float vd = leaky(av + g_bdes[c]);
                float vn = g_bnum[c];
#pragma unroll
                for (int k = 0; k < 5; k++) vn += nbuf[k] * g_Wnum[k * HH + c];
                vn = leaky(vn);
                float vc = g_bcat[c];
#pragma unroll
                for (int k = 0; k < 6; k++) vc += cbuf[k] * g_Wcat[k * HH + c];
                vc = leaky(vc);
                res[i] = vd + vn + vc;
            }
            g_xv[grow * 16 + tx] = make_float4(res[0], res[1], res[2], res[3]);
        }
    }
}

// ---------------- scatter: 2 edges per thread for MLP, vectorized global reductions ----------------
__global__ void scatter_kernel(const int* __restrict__ ei, const int* __restrict__ et)
{
    const int HALF = EE / 2;
    int gid = blockIdx.x * 256 + threadIdx.x;     // HALF*16 threads total
    int e0 = gid >> 4;
    int lane = gid & 15;
    int e1 = e0 + HALF;

    int s0 = ei[e0];
    int s1 = ei[e1];
    int d0 = ei[EE + e0];
    int d1 = ei[EE + e1];
    int t0 = et[e0];
    int t1 = et[e1];
    float4 v0 = g_xv[s0 * 16 + lane];
    float4 v1 = g_xv[s1 * 16 + lane];

    float* a0 = (float*)&g_Av[t0][d0 * 16 + lane];
    asm volatile("red.global.add.v4.f32 [%0], {%1, %2, %3, %4};"
                 :: "l"(a0), "f"(v0.x), "f"(v0.y), "f"(v0.z), "f"(v0.w) : "memory");
    float* a1 = (float*)&g_Av[t1][d1 * 16 + lane];
    asm volatile("red.global.add.v4.f32 [%0], {%1, %2, %3, %4};"
                 :: "l"(a1), "f"(v1.x), "f"(v1.y), "f"(v1.z), "f"(v1.w) : "memory");
    if (lane == 0) {
        atomicAdd(&g_cnt[t0][d0], 1);
        atomicAdd(&g_cnt[t1][d1], 1);
    }
}

// ---------------- finalA: Z = leaky((S0@W0*inv0 + S1@W1*inv1)*0.5), GEMM N x 64, K=128 ----------------
// Same microtile as feat; two accumulator sets (one per relation); writes Z into g_xv.
__global__ __launch_bounds__(256) void finalA_kernel()
{
    __shared__ float As[2][16][132];
    __shared__ float Bs[2][16][64];
    int tid = threadIdx.x;
    int tx = tid & 15;
    int ty = tid >> 4;
    int row0 = blockIdx.x * 128;
    int c0 = tx * 4;
    int rl = ty * 8;

    int r0 = tid >> 2, kq0 = tid & 3;
    int r1 = (tid + 256) >> 2;
    int kb = tid >> 4, cb = (tid & 15) * 4;

    ull accR0[4][4], accR1[4][4];
#pragma unroll
    for (int j = 0; j < 4; j++)
#pragma unroll
        for (int i = 0; i < 4; i++) { accR0[j][i] = 0ull; accR1[j][i] = 0ull; }

    float4 pA0, pA1, pB;
    auto gload = [&](int kk) {
        int kcat = kk + kq0 * 4;
        int rel = kcat >> 6;
        int offq = (kcat & 63) >> 2;
        int g0 = row0 + r0, g1 = row0 + r1;
        pA0 = (g0 < NN) ? g_Av[rel][g0 * 16 + offq] : make_float4(0.f, 0.f, 0.f, 0.f);
        pA1 = (g1 < NN) ? g_Av[rel][g1 * 16 + offq] : make_float4(0.f, 0.f, 0.f, 0.f);
        int kB = kk + kb;
        pB = *(const float4*)&g_Wr[kB >> 6][(kB & 63) * HH + cb];
    };
    auto sstore = [&](int buf) {
        As[buf][kq0 * 4 + 0][r0] = pA0.x;
        As[buf][kq0 * 4 + 1][r0] = pA0.y;
        As[buf][kq0 * 4 + 2][r0] = pA0.z;
        As[buf][kq0 * 4 + 3][r0] = pA0.w;
        As[buf][kq0 * 4 + 0][r1] = pA1.x;
        As[buf][kq0 * 4 + 1][r1] = pA1.y;
        As[buf][kq0 * 4 + 2][r1] = pA1.z;
        As[buf][kq0 * 4 + 3][r1] = pA1.w;
        *(float4*)&Bs[buf][kb][cb] = pB;
    };

    gload(0);
    sstore(0);
    __syncthreads();

#pragma unroll
    for (int t = 0; t < 8; t++) {
        int buf = t & 1;
        if (t + 1 < 8) gload((t + 1) * 16);
        ull (&acc)[4][4] = (t < 4) ? accR0 : accR1;
#pragma unroll
        for (int k = 0; k < 16; k++) {
            float4 b4 = *(const float4*)&Bs[buf][k][c0];
            ull bd0 = dupf(b4.x), bd1 = dupf(b4.y), bd2 = dupf(b4.z), bd3 = dupf(b4.w);
            ulonglong2 a01 = *(const ulonglong2*)&As[buf][k][rl];
            ulonglong2 a23 = *(const ulonglong2*)&As[buf][k][rl + 4];
            fma2(acc[0][0], a01.x, bd0); fma2(acc[0][1], a01.x, bd1);
            fma2(acc[0][2], a01.x, bd2); fma2(acc[0][3], a01.x, bd3);
            fma2(acc[1][0], a01.y, bd0); fma2(acc[1][1], a01.y, bd1);
            fma2(acc[1][2], a01.y, bd2); fma2(acc[1][3], a01.y, bd3);
            fma2(acc[2][0], a23.x, bd0); fma2(acc[2][1], a23.x, bd1);
            fma2(acc[2][2], a23.x, bd2); fma2(acc[2][3], a23.x, bd3);
            fma2(acc[3][0], a23.y, bd0); fma2(acc[3][1], a23.y, bd1);
            fma2(acc[3][2], a23.y, bd2); fma2(acc[3][3], a23.y, bd3);
        }
        if (t + 1 < 8) sstore((t + 1) & 1);
        __syncthreads();
    }

#pragma unroll
    for (int j = 0; j < 8; j++) {
        int grow = row0 + rl + j;
        if (grow < NN) {
            int jp = j >> 1, hi = j & 1;
            float inv0 = 1.f / (float)max(g_cnt[0][grow], 1);
            float inv1 = 1.f / (float)max(g_cnt[1][grow], 1);
            float res[4];
#pragma unroll
            for (int i = 0; i < 4; i++) {
                float2 u0 = unpk(accR0[jp][i]);
                float2 u1 = unpk(accR1[jp][i]);
                float v0 = hi ? u0.y : u0.x;
                float v1 = hi ? u1.y : u1.x;
                res[i] = leaky((v0 * inv0 + v1 * inv1) * 0.5f);
            }
            g_xv[grow * 16 + tx] = make_float4(res[0], res[1], res[2], res[3]);
        }
    }
}

// ---------------- finalB: classifier, one thread per node ----------------
__global__ __launch_bounds__(256) void finalB_kernel(const float* __restrict__ W1,
                                                     const float* __restrict__ b1,
                                                     const float* __restrict__ W2,
                                                     const float* __restrict__ b2,
                                                     float* __restrict__ out)
{
    __shared__ ull   C1p[64][16];   // C1p[k][p] = (W1[2p][k], W1[2p+1][k])
    __shared__ float C2s[64];       // [0..31]=W2[0][:], [32..63]=W2[1][:]
    __shared__ float B1s[32];

    int tid = threadIdx.x;
    for (int idx = tid; idx < 1024; idx += 256) {
        int k = idx >> 4, p = idx & 15;
        C1p[k][p] = pk2(W1[(2 * p) * 64 + k], W1[(2 * p + 1) * 64 + k]);
    }
    if (tid < 64) C2s[tid] = W2[tid];
    if (tid < 32) B1s[tid] = b1[tid];
    __syncthreads();

    int n = blockIdx.x * 256 + tid;
    if (n >= NN) return;

    ull hacc[16];
#pragma unroll
    for (int p = 0; p < 16; p++) hacc[p] = 0ull;

    for (int kq = 0; kq < 16; kq++) {
        float4 z4 = g_xv[n * 16 + kq];
        float zc[4] = {z4.x, z4.y, z4.z, z4.w};
#pragma unroll
        for (int c = 0; c < 4; c++) {
            int k = kq * 4 + c;
            ull zd = dupf(zc[c]);
            const ulonglong2* wv = (const ulonglong2*)&C1p[k][0];
#pragma unroll
            for (int p2 = 0; p2 < 8; p2++) {
                ulonglong2 w = wv[p2];
                fma2(hacc[2 * p2 + 0], zd, w.x);
                fma2(hacc[2 * p2 + 1], zd, w.y);
            }
        }
    }

    float q0 = 0.f, q1 = 0.f;
#pragma unroll
    for (int p = 0; p < 16; p++) {
        float2 u = unpk(hacc[p]);
        float h0 = leaky(u.x + B1s[2 * p]);
        float h1 = leaky(u.y + B1s[2 * p + 1]);
        q0 += h0 * C2s[2 * p] + h1 * C2s[2 * p + 1];
        q1 += h0 * C2s[32 + 2 * p] + h1 * C2s[32 + 2 * p + 1];
    }
    out[n * 2 + 0] = q0 + b2[0];
    out[n * 2 + 1] = q1 + b2[1];
}

// ---------------- launch ----------------
extern "C" void kernel_launch(void* const* d_in, const int* in_sizes, int n_in,
                              void* d_out, int out_size)
{
    const float* des     = (const float*)d_in[0];
    const float* num     = (const float*)d_in[1];
    const float* cat     = (const float*)d_in[2];
    const int*   ei      = (const int*)d_in[3];
    const int*   et      = (const int*)d_in[4];
    const float* desW    = (const float*)d_in[5];
    const float* desb    = (const float*)d_in[6];
    const float* numW    = (const float*)d_in[7];
    const float* numb    = (const float*)d_in[8];
    const float* catW    = (const float*)d_in[9];
    const float* catb    = (const float*)d_in[10];
    const float* desg    = (const float*)d_in[11];
    const float* desbeta = (const float*)d_in[12];
    const float* desm    = (const float*)d_in[13];
    const float* desv    = (const float*)d_in[14];
    const float* numg    = (const float*)d_in[15];
    const float* numbeta = (const float*)d_in[16];
    const float* numm    = (const float*)d_in[17];
    const float* numv    = (const float*)d_in[18];
    const float* catg    = (const float*)d_in[19];
    const float* catbeta = (const float*)d_in[20];
    const float* catm    = (const float*)d_in[21];
    const float* catv    = (const float*)d_in[22];
    const float* rgcnW   = (const float*)d_in[23];
    const float* clsW1   = (const float*)d_in[24];
    const float* clsb1   = (const float*)d_in[25];
    const float* clsW2   = (const float*)d_in[26];
    const float* clsb2   = (const float*)d_in[27];
    float* out = (float*)d_out;

    prep_kernel<<<(KDES * HH + 255) / 256, 256>>>(
        desW, desb, numW, numb, catW, catb,
        desg, desbeta, desm, desv,
        numg, numbeta, numm, numv,
        catg, catbeta, catm, catv,
        rgcnW);

    zero_kernel<<<(2 * NN * 16 + 2 * NN + 255) / 256, 256>>>();

    feat_kernel<<<(NN + 127) / 128, 256>>>(des, num, cat);

    scatter_kernel<<<(EE / 2 * 16) / 256, 256>>>(ei, et);

    finalA_kernel<<<(NN + 127) / 128, 256>>>();

    finalB_kernel<<<(NN + 255) / 256, 256>>>(clsW1, clsb1, clsW2, clsb2, out);
}

// round 5
// speedup vs baseline: 3.5641x; 1.2401x over previous
#include <cuda_runtime.h>
#include <cuda_bf16.h>
#include <mma.h>
#include <cstdint>

using namespace nvcuda;

#define NN   100000
#define EE   3200000
#define HH   64
#define KDES 768
#define RNEG 0.01f
#define BNEPS 1e-5f

typedef unsigned long long ull;

// ---------------- scratch (static __device__ globals; no allocation) ----------------
__device__ float4 g_xv[NN * 16];          // node features x [N,64]; later reused for Z
__device__ float4 g_Av[2][NN * 16];       // per-relation raw sums [N,64]
__device__ int    g_cnt[2][NN];           // per-relation in-degree counts
__device__ float  g_bdes[HH];
__device__ float  g_Wnum[5 * HH];
__device__ float  g_bnum[HH];
__device__ float  g_Wcat[6 * HH];
__device__ float  g_bcat[HH];
__device__ float  g_Wr[2][HH * HH];       // rgcn weights, k-major
// bf16-split BN-folded des weight, k-major [768][64]
__device__ unsigned short g_Bh[KDES * HH];
__device__ unsigned short g_Bl[KDES * HH];

__device__ __forceinline__ float leaky(float v) { return v > 0.f ? v : RNEG * v; }

// packed f32x2 helpers (finalA/finalB)
__device__ __forceinline__ void fma2(ull& d, ull a, ull b) {
    asm("fma.rn.f32x2 %0, %1, %2, %0;" : "+l"(d) : "l"(a), "l"(b));
}
__device__ __forceinline__ ull dupf(float x) {
    ull r; asm("mov.b64 %0, {%1, %1};" : "=l"(r) : "f"(x)); return r;
}
__device__ __forceinline__ ull pk2(float a, float b) {
    ull r; asm("mov.b64 %0, {%1, %2};" : "=l"(r) : "f"(a), "f"(b)); return r;
}
__device__ __forceinline__ float2 unpk(ull v) {
    float2 r; asm("mov.b64 {%0, %1}, %2;" : "=f"(r.x), "=f"(r.y) : "l"(v)); return r;
}

// pack two floats to bf16x2: low 16 = bf16(lo), high 16 = bf16(hi)
__device__ __forceinline__ uint32_t bfpack(float lo, float hi) {
    uint32_t r;
    asm("cvt.rn.bf16x2.f32 %0, %1, %2;" : "=r"(r) : "f"(hi), "f"(lo));
    return r;
}

// ---------------- prep: fold BN, build bf16-split B, transpose Wr ----------------
__global__ void prep_kernel(const float* __restrict__ desW, const float* __restrict__ desb,
                            const float* __restrict__ numW, const float* __restrict__ numb,
                            const float* __restrict__ catW, const float* __restrict__ catb,
                            const float* __restrict__ desg, const float* __restrict__ desbeta,
                            const float* __restrict__ desm, const float* __restrict__ desv,
                            const float* __restrict__ numg, const float* __restrict__ numbeta,
                            const float* __restrict__ numm, const float* __restrict__ numv,
                            const float* __restrict__ catg, const float* __restrict__ catbeta,
                            const float* __restrict__ catm, const float* __restrict__ catv,
                            const float* __restrict__ rgcnW)
{
    int idx = blockIdx.x * blockDim.x + threadIdx.x;
    if (idx < KDES * HH) {
        int k = idx >> 6, n = idx & 63;
        float s = desg[n] * rsqrtf(desv[n] + BNEPS);
        float w = desW[n * KDES + k] * s;
        uint32_t hp = bfpack(w, 0.f);
        float hf = __uint_as_float(hp << 16);
        uint32_t lp = bfpack(w - hf, 0.f);
        g_Bh[k * HH + n] = (unsigned short)(hp & 0xffffu);
        g_Bl[k * HH + n] = (unsigned short)(lp & 0xffffu);
    }
    if (idx < 5 * HH) {
        int k = idx >> 6, h = idx & 63;
        float s = numg[h] * rsqrtf(numv[h] + BNEPS);
        g_Wnum[k * HH + h] = numW[h * 5 + k] * s;
    }
    if (idx < 6 * HH) {
        int k = idx >> 6, h = idx & 63;
        float s = catg[h] * rsqrtf(catv[h] + BNEPS);
        g_Wcat[k * HH + h] = catW[h * 6 + k] * s;
    }
    if (idx < 2 * HH * HH) {
        int r = idx >> 12;
        int rem = idx & 4095;
        int h = rem >> 6, k = rem & 63;
        g_Wr[r][k * HH + h] = rgcnW[r * HH * HH + h * HH + k];
    }
    if (idx < HH) {
        int h = idx;
        float sd = desg[h] * rsqrtf(desv[h] + BNEPS);
        g_bdes[h] = (desb[h] - desm[h]) * sd + desbeta[h];
        float sn = numg[h] * rsqrtf(numv[h] + BNEPS);
        g_bnum[h] = (numb[h] - numm[h]) * sn + numbeta[h];
        float sc = catg[h] * rsqrtf(catv[h] + BNEPS);
        g_bcat[h] = (catb[h] - catm[h]) * sc + catbeta[h];
    }
}

// ---------------- zero accumulators + counts ----------------
__global__ void zero_kernel()
{
    int idx = blockIdx.x * blockDim.x + threadIdx.x;
    const int NV = 2 * NN * 16;
    if (idx < NV) {
        ((float4*)g_Av)[idx] = make_float4(0.f, 0.f, 0.f, 0.f);
    } else {
        int j = idx - NV;
        if (j < 2 * NN) ((int*)g_cnt)[j] = 0;
    }
}

// ---------------- feat: WMMA bf16x3-split GEMM, CTA tile 128x64, K=768 in 48 chunks of 16 ----------------
// dynamic smem (bytes):
//   AH @ 0      : [2][128][24] bf16 = 12288
//   AL @ 12288  : [2][128][24] bf16 = 12288
//   BH @ 24576  : [2][16][72]  bf16 = 4608
//   BL @ 29184  : [2][16][72]  bf16 = 4608   (A/B end at 33792)
//   D  @ 0      : [128][68] f32 = 34816      (overlaps A/B; used only after last MMA)
//   TAB@ 34816  : 896 floats = 3584
#define ALD 24
#define BLD 72
#define DLD 68
#define F_OFF_AH 0u
#define F_OFF_AL 12288u
#define F_OFF_BH 24576u
#define F_OFF_BL 29184u
#define F_OFF_D  0u
#define F_OFF_TAB 34816u
#define F_SMEM_TOTAL (34816 + 3584)

__global__ __launch_bounds__(256) void feat_kernel(const float* __restrict__ des,
                                                   const float* __restrict__ num,
                                                   const float* __restrict__ cat)
{
    extern __shared__ __align__(128) char sm[];
    __nv_bfloat16* AH = (__nv_bfloat16*)(sm + F_OFF_AH);
    __nv_bfloat16* AL = (__nv_bfloat16*)(sm + F_OFF_AL);
    __nv_bfloat16* BH = (__nv_bfloat16*)(sm + F_OFF_BH);
    __nv_bfloat16* BL = (__nv_bfloat16*)(sm + F_OFF_BL);
    float* Df  = (float*)(sm + F_OFF_D);
    float* tab = (float*)(sm + F_OFF_TAB);

    int tid = threadIdx.x;
    int warp = tid >> 5;
    int wr = warp >> 1;       // 0..3 (M)
    int wc = warp & 1;        // 0..1 (N)
    int row0 = blockIdx.x * 128;

    // stage epilogue tables
    for (int i = tid; i < 896; i += 256) {
        float v;
        if (i < 64) v = g_bdes[i];
        else if (i < 128) v = g_bnum[i - 64];
        else if (i < 192) v = g_bcat[i - 128];
        else if (i < 512) v = g_Wnum[i - 192];
        else v = g_Wcat[i - 512];
        tab[i] = v;
    }

    wmma::fragment<wmma::accumulator, 16, 16, 16, float> acc[2][2];
#pragma unroll
    for (int i = 0; i < 2; i++)
#pragma unroll
        for (int j = 0; j < 2; j++) wmma::fill_fragment(acc[i][j], 0.f);

    auto produceA = [&](int t, int b) {
        int kk = t * 16;
#pragma unroll
        for (int i = 0; i < 2; i++) {
            int u = tid + 256 * i;      // float4 slot 0..511
            int row = u >> 2;           // 0..127
            int q = u & 3;              // float4 within the 16-k row
            int grow = row0 + row;
            float4 f = make_float4(0.f, 0.f, 0.f, 0.f);
            if (grow < NN) f = *(const float4*)&des[(size_t)grow * KDES + kk + q * 4];
            uint32_t h0 = bfpack(f.x, f.y);
            uint32_t h1 = bfpack(f.z, f.w);
            uint32_t l0 = bfpack(f.x - __uint_as_float(h0 << 16),
                                 f.y - __uint_as_float(h0 & 0xffff0000u));
            uint32_t l1 = bfpack(f.z - __uint_as_float(h1 << 16),
                                 f.w - __uint_as_float(h1 & 0xffff0000u));
            int eoff = (b * 128 + row) * ALD + q * 4;
            *(uint2*)&AH[eoff] = make_uint2(h0, h1);
            *(uint2*)&AL[eoff] = make_uint2(l0, l1);
        }
    };
    auto copyB = [&](int t, int b) {
        int i = tid * 4;                // element index, 1024 total
        int r = i >> 6, c = i & 63;
        uint2 vh = *(const uint2*)&g_Bh[(t * 16 + r) * HH + c];
        uint2 vl = *(const uint2*)&g_Bl[(t * 16 + r) * HH + c];
        int eoff = (b * 16 + r) * BLD + c;
        *(uint2*)&BH[eoff] = vh;
        *(uint2*)&BL[eoff] = vl;
    };
    auto domma = [&](int b) {
        wmma::fragment<wmma::matrix_a, 16, 16, 16, __nv_bfloat16, wmma::row_major> ah[2], al[2];
        wmma::fragment<wmma::matrix_b, 16, 16, 16, __nv_bfloat16, wmma::row_major> bh[2], bl[2];
#pragma unroll
        for (int i = 0; i < 2; i++) {
            int base = (b * 128 + wr * 32 + i * 16) * ALD;
            wmma::load_matrix_sync(ah[i], AH + base, ALD);
            wmma::load_matrix_sync(al[i], AL + base, ALD);
        }
#pragma unroll
        for (int j = 0; j < 2; j++) {
            int base = (b * 16) * BLD + wc * 32 + j * 16;
            wmma::load_matrix_sync(bh[j], BH + base, BLD);
            wmma::load_matrix_sync(bl[j], BL + base, BLD);
        }
#pragma unroll
        for (int i = 0; i < 2; i++)
#pragma unroll
            for (int j = 0; j < 2; j++) {
                wmma::mma_sync(acc[i][j], ah[i], bh[j], acc[i][j]);
                wmma::mma_sync(acc[i][j], ah[i], bl[j], acc[i][j]);
                wmma::mma_sync(acc[i][j], al[i], bh[j], acc[i][j]);
            }
    };

    produceA(0, 0);
    copyB(0, 0);
    __syncthreads();

    const int T = KDES / 16;   // 48
    for (int t = 0; t < T; t++) {
        int b = t & 1;
        if (t + 1 < T) { produceA(t + 1, 1 - b); copyB(t + 1, 1 - b); }
        domma(b);
        __syncthreads();
    }

    // stage D to smem (overlaps A/B; all MMAs done after the final sync above)
#pragma unroll
    for (int i = 0; i < 2; i++)
#pragma unroll
        for (int j = 0; j < 2; j++)
            wmma::store_matrix_sync(Df + (wr * 32 + i * 16) * DLD + wc * 32 + j * 16,
                                    acc[i][j], DLD, wmma::mem_row_major);
    __syncthreads();

    // epilogue: each thread handles half a row (32 cols)
    {
        int row = tid >> 1;
        int ch = (tid & 1) * 8;         // float4 index base within row
        int grow = row0 + row;
        if (grow < NN) {
            float nb[5], cb[6];
#pragma unroll
            for (int j = 0; j < 5; j++) nb[j] = num[grow * 5 + j];
#pragma unroll
            for (int j = 0; j < 6; j++) cb[j] = cat[grow * 6 + j];
            const float4* bd4 = (const float4*)tab;
            const float4* bn4 = (const float4*)(tab + 64);
            const float4* bc4 = (const float4*)(tab + 128);
#pragma unroll
            for (int cq = 0; cq < 8; cq++) {
                int cqq = ch + cq;
                float4 d = *(const float4*)&Df[row * DLD + cqq * 4];
                float4 bd = bd4[cqq];
                float4 bn = bn4[cqq];
                float4 bc = bc4[cqq];
                float vn[4] = {bn.x, bn.y, bn.z, bn.w};
                float vc[4] = {bc.x, bc.y, bc.z, bc.w};
#pragma unroll
                for (int j = 0; j < 5; j++) {
                    float4 w = ((const float4*)(tab + 192 + j * 64))[cqq];
                    vn[0] += nb[j] * w.x; vn[1] += nb[j] * w.y;
                    vn[2] += nb[j] * w.z; vn[3] += nb[j] * w.w;
                }
#pragma unroll
                for (int j = 0; j < 6; j++) {
                    float4 w = ((const float4*)(tab + 512 + j * 64))[cqq];
                    vc[0] += cb[j] * w.x; vc[1] += cb[j] * w.y;
                    vc[2] += cb[j] * w.z; vc[3] += cb[j] * w.w;
                }
                float4 res;
                res.x = leaky(d.x + bd.x) + leaky(vn[0]) + leaky(vc[0]);
                res.y = leaky(d.y + bd.y) + leaky(vn[1]) + leaky(vc[1]);
                res.z = leaky(d.z + bd.z) + leaky(vn[2]) + leaky(vc[2]);
                res.w = leaky(d.w + bd.w) + leaky(vn[3]) + leaky(vc[3]);
                g_xv[grow * 16 + cqq] = res;
            }
        }
    }
}

// ---------------- scatter: 2 edges per thread for MLP, vectorized global reductions ----------------
__global__ void scatter_kernel(const int* __restrict__ ei, const int* __restrict__ et)
{
    const int HALF = EE / 2;
    int gid = blockIdx.x * 256 + threadIdx.x;
    int e0 = gid >> 4;
    int lane = gid & 15;
    int e1 = e0 + HALF;

    int s0 = ei[e0];
    int s1 = ei[e1];
    int d0 = ei[EE + e0];
    int d1 = ei[EE + e1];
    int t0 = et[e0];
    int t1 = et[e1];
    float4 v0 = g_xv[s0 * 16 + lane];
    float4 v1 = g_xv[s1 * 16 + lane];

    float* a0 = (float*)&g_Av[t0][d0 * 16 + lane];
    asm volatile("red.global.add.v4.f32 [%0], {%1, %2, %3, %4};"
                 :: "l"(a0), "f"(v0.x), "f"(v0.y), "f"(v0.z), "f"(v0.w) : "memory");
    float* a1 = (float*)&g_Av[t1][d1 * 16 + lane];
    asm volatile("red.global.add.v4.f32 [%0], {%1, %2, %3, %4};"
                 :: "l"(a1), "f"(v1.x), "f"(v1.y), "f"(v1.z), "f"(v1.w) : "memory");
    if (lane == 0) {
        atomicAdd(&g_cnt[t0][d0], 1);
        atomicAdd(&g_cnt[t1][d1], 1);
    }
}

// ---------------- finalA: Z = leaky((S0@W0*inv0 + S1@W1*inv1)*0.5) ----------------
__global__ __launch_bounds__(256) void finalA_kernel()
{
    __shared__ float As[2][16][132];
    __shared__ float Bs[2][16][64];
    int tid = threadIdx.x;
    int tx = tid & 15;
    int ty = tid >> 4;
    int row0 = blockIdx.x * 128;
    int c0 = tx * 4;
    int rl = ty * 8;

    int r0 = tid >> 2, kq0 = tid & 3;
    int r1 = (tid + 256) >> 2;
    int kb = tid >> 4, cb = (tid & 15) * 4;

    ull accR0[4][4], accR1[4][4];
#pragma unroll
    for (int j = 0; j < 4; j++)
#pragma unroll
        for (int i = 0; i < 4; i++) { accR0[j][i] = 0ull; accR1[j][i] = 0ull; }

    float4 pA0, pA1, pB;
    auto gload = [&](int kk) {
        int kcat = kk + kq0 * 4;
        int rel = kcat >> 6;
        int offq = (kcat & 63) >> 2;
        int g0 = row0 + r0, g1 = row0 + r1;
        pA0 = (g0 < NN) ? g_Av[rel][g0 * 16 + offq] : make_float4(0.f, 0.f, 0.f, 0.f);
        pA1 = (g1 < NN) ? g_Av[rel][g1 * 16 + offq] : make_float4(0.f, 0.f, 0.f, 0.f);
        int kB = kk + kb;
        pB = *(const float4*)&g_Wr[kB >> 6][(kB & 63) * HH + cb];
    };
    auto sstore = [&](int buf) {
        As[buf][kq0 * 4 + 0][r0] = pA0.x;
        As[buf][kq0 * 4 + 1][r0] = pA0.y;
        As[buf][kq0 * 4 + 2][r0] = pA0.z;
        As[buf][kq0 * 4 + 3][r0] = pA0.w;
        As[buf][kq0 * 4 + 0][r1] = pA1.x;
        As[buf][kq0 * 4 + 1][r1] = pA1.y;
        As[buf][kq0 * 4 + 2][r1] = pA1.z;
        As[buf][kq0 * 4 + 3][r1] = pA1.w;
        *(float4*)&Bs[buf][kb][cb] = pB;
    };

    gload(0);
    sstore(0);
    __syncthreads();

#pragma unroll
    for (int t = 0; t < 8; t++) {
        int buf = t & 1;
        if (t + 1 < 8) gload((t + 1) * 16);
        ull (&acc)[4][4] = (t < 4) ? accR0 : accR1;
#pragma unroll
        for (int k = 0; k < 16; k++) {
            float4 b4 = *(const float4*)&Bs[buf][k][c0];
            ull bd0 = dupf(b4.x), bd1 = dupf(b4.y), bd2 = dupf(b4.z), bd3 = dupf(b4.w);
            ulonglong2 a01 = *(const ulonglong2*)&As[buf][k][rl];
            ulonglong2 a23 = *(const ulonglong2*)&As[buf][k][rl + 4];
            fma2(acc[0][0], a01.x, bd0); fma2(acc[0][1], a01.x, bd1);
            fma2(acc[0][2], a01.x, bd2); fma2(acc[0][3], a01.x, bd3);
            fma2(acc[1][0], a01.y, bd0); fma2(acc[1][1], a01.y, bd1);
            fma2(acc[1][2], a01.y, bd2); fma2(acc[1][3], a01.y, bd3);
            fma2(acc[2][0], a23.x, bd0); fma2(acc[2][1], a23.x, bd1);
            fma2(acc[2][2], a23.x, bd2); fma2(acc[2][3], a23.x, bd3);
            fma2(acc[3][0], a23.y, bd0); fma2(acc[3][1], a23.y, bd1);
            fma2(acc[3][2], a23.y, bd2); fma2(acc[3][3], a23.y, bd3);
        }
        if (t + 1 < 8) sstore((t + 1) & 1);
        __syncthreads();
    }

#pragma unroll
    for (int j = 0; j < 8; j++) {
        int grow = row0 + rl + j;
        if (grow < NN) {
            int jp = j >> 1, hi = j & 1;
            float inv0 = 1.f / (float)max(g_cnt[0][grow], 1);
            float inv1 = 1.f / (float)max(g_cnt[1][grow], 1);
            float res[4];
#pragma unroll
            for (int i = 0; i < 4; i++) {
                float2 u0 = unpk(accR0[jp][i]);
                float2 u1 = unpk(accR1[jp][i]);
                float v0 = hi ? u0.y : u0.x;
                float v1 = hi ? u1.y : u1.x;
                res[i] = leaky((v0 * inv0 + v1 * inv1) * 0.5f);
            }
            g_xv[grow * 16 + tx] = make_float4(res[0], res[1], res[2], res[3]);
        }
    }
}

// ---------------- finalB: classifier, one thread per node ----------------
__global__ __launch_bounds__(256) void finalB_kernel(const float* __restrict__ W1,
                                                     const float* __restrict__ b1,
                                                     const float* __restrict__ W2,
                                                     const float* __restrict__ b2,
                                                     float* __restrict__ out)
{
    __shared__ ull   C1p[64][16];
    __shared__ float C2s[64];
    __shared__ float B1s[32];

    int tid = threadIdx.x;
    for (int idx = tid; idx < 1024; idx += 256) {
        int k = idx >> 4, p = idx & 15;
        C1p[k][p] = pk2(W1[(2 * p) * 64 + k], W1[(2 * p + 1) * 64 + k]);
    }
    if (tid < 64) C2s[tid] = W2[tid];
    if (tid < 32) B1s[tid] = b1[tid];
    __syncthreads();

    int n = blockIdx.x * 256 + tid;
    if (n >= NN) return;

    ull hacc[16];
#pragma unroll
    for (int p = 0; p < 16; p++) hacc[p] = 0ull;

    for (int kq = 0; kq < 16; kq++) {
        float4 z4 = g_xv[n * 16 + kq];
        float zc[4] = {z4.x, z4.y, z4.z, z4.w};
#pragma unroll
        for (int c = 0; c < 4; c++) {
            int k = kq * 4 + c;
            ull zd = dupf(zc[c]);
            const ulonglong2* wv = (const ulonglong2*)&C1p[k][0];
#pragma unroll
            for (int p2 = 0; p2 < 8; p2++) {
                ulonglong2 w = wv[p2];
                fma2(hacc[2 * p2 + 0], zd, w.x);
                fma2(hacc[2 * p2 + 1], zd, w.y);
            }
        }
    }

    float q0 = 0.f, q1 = 0.f;
#pragma unroll
    for (int p = 0; p < 16; p++) {
        float2 u = unpk(hacc[p]);
        float h0 = leaky(u.x + B1s[2 * p]);
        float h1 = leaky(u.y + B1s[2 * p + 1]);
        q0 += h0 * C2s[2 * p] + h1 * C2s[2 * p + 1];
        q1 += h0 * C2s[32 + 2 * p] + h1 * C2s[32 + 2 * p + 1];
    }
    out[n * 2 + 0] = q0 + b2[0];
    out[n * 2 + 1] = q1 + b2[1];
}

// ---------------- launch ----------------
extern "C" void kernel_launch(void* const* d_in, const int* in_sizes, int n_in,
                              void* d_out, int out_size)
{
    const float* des     = (const float*)d_in[0];
    const float* num     = (const float*)d_in[1];
    const float* cat     = (const float*)d_in[2];
    const int*   ei      = (const int*)d_in[3];
    const int*   et      = (const int*)d_in[4];
    const float* desW    = (const float*)d_in[5];
    const float* desb    = (const float*)d_in[6];
    const float* numW    = (const float*)d_in[7];
    const float* numb    = (const float*)d_in[8];
    const float* catW    = (const float*)d_in[9];
    const float* catb    = (const float*)d_in[10];
    const float* desg    = (const float*)d_in[11];
    const float* desbeta = (const float*)d_in[12];
    const float* desm    = (const float*)d_in[13];
    const float* desv    = (const float*)d_in[14];
    const float* numg    = (const float*)d_in[15];
    const float* numbeta = (const float*)d_in[16];
    const float* numm    = (const float*)d_in[17];
    const float* numv    = (const float*)d_in[18];
    const float* catg    = (const float*)d_in[19];
    const float* catbeta = (const float*)d_in[20];
    const float* catm    = (const float*)d_in[21];
    const float* catv    = (const float*)d_in[22];
    const float* rgcnW   = (const float*)d_in[23];
    const float* clsW1   = (const float*)d_in[24];
    const float* clsb1   = (const float*)d_in[25];
    const float* clsW2   = (const float*)d_in[26];
    const float* clsb2   = (const float*)d_in[27];
    float* out = (float*)d_out;

    prep_kernel<<<(KDES * HH + 255) / 256, 256>>>(
        desW, desb, numW, numb, catW, catb,
        desg, desbeta, desm, desv,
        numg, numbeta, numm, numv,
        catg, catbeta, catm, catv,
        rgcnW);

    zero_kernel<<<(2 * NN * 16 + 2 * NN + 255) / 256, 256>>>();

    feat_kernel<<<(NN + 127) / 128, 256, F_SMEM_TOTAL>>>(des, num, cat);

    scatter_kernel<<<(EE / 2 * 16) / 256, 256>>>(ei, et);

    finalA_kernel<<<(NN + 127) / 128, 256>>>();

    finalB_kernel<<<(NN + 255) / 256, 256>>>(clsW1, clsb1, clsW2, clsb2, out);
}

// round 6
// speedup vs baseline: 3.8304x; 1.0747x over previous
#include <cuda_runtime.h>
#include <cuda_bf16.h>
#include <mma.h>
#include <cstdint>

using namespace nvcuda;

#define NN   100000
#define EE   3200000
#define HH   64
#define KDES 768
#define RNEG 0.01f
#define BNEPS 1e-5f
#define CAP  96

typedef unsigned long long ull;

// ---------------- scratch (static __device__ globals; no allocation) ----------------
__device__ float4 g_xv[NN * 16];          // node features x [N,64]; later reused for Z
__device__ float4 g_Av[2][NN * 16];       // per-relation MEAN vectors [N,64]
__device__ int    g_cnt0[NN];             // relation-0 in-degree
__device__ int    g_ctot[NN];             // total in-degree (cursor during build)
__device__ uint32_t g_bucket[NN * CAP];   // per-dst edge payloads: src | rel<<17
__device__ float  g_bdes[HH];
__device__ float  g_Wnum[5 * HH];
__device__ float  g_bnum[HH];
__device__ float  g_Wcat[6 * HH];
__device__ float  g_bcat[HH];
__device__ float  g_Wr[2][HH * HH];       // rgcn weights, k-major (contiguous = [128][64])
// bf16-split BN-folded des weight, k-major [768][64]
__device__ unsigned short g_Bh[KDES * HH];
__device__ unsigned short g_Bl[KDES * HH];

__device__ __forceinline__ float leaky(float v) { return v > 0.f ? v : RNEG * v; }

// packed f32x2 helpers
__device__ __forceinline__ void fma2(ull& d, ull a, ull b) {
    asm("fma.rn.f32x2 %0, %1, %2, %0;" : "+l"(d) : "l"(a), "l"(b));
}
__device__ __forceinline__ ull dupf(float x) {
    ull r; asm("mov.b64 %0, {%1, %1};" : "=l"(r) : "f"(x)); return r;
}
__device__ __forceinline__ ull pk2(float a, float b) {
    ull r; asm("mov.b64 %0, {%1, %2};" : "=l"(r) : "f"(a), "f"(b)); return r;
}
__device__ __forceinline__ float2 unpk(ull v) {
    float2 r; asm("mov.b64 {%0, %1}, %2;" : "=f"(r.x), "=f"(r.y) : "l"(v)); return r;
}
__device__ __forceinline__ uint32_t bfpack(float lo, float hi) {
    uint32_t r;
    asm("cvt.rn.bf16x2.f32 %0, %1, %2;" : "=r"(r) : "f"(hi), "f"(lo));
    return r;
}

// ---------------- prep ----------------
__global__ void prep_kernel(const float* __restrict__ desW, const float* __restrict__ desb,
                            const float* __restrict__ numW, const float* __restrict__ numb,
                            const float* __restrict__ catW, const float* __restrict__ catb,
                            const float* __restrict__ desg, const float* __restrict__ desbeta,
                            const float* __restrict__ desm, const float* __restrict__ desv,
                            const float* __restrict__ numg, const float* __restrict__ numbeta,
                            const float* __restrict__ numm, const float* __restrict__ numv,
                            const float* __restrict__ catg, const float* __restrict__ catbeta,
                            const float* __restrict__ catm, const float* __restrict__ catv,
                            const float* __restrict__ rgcnW)
{
    int idx = blockIdx.x * blockDim.x + threadIdx.x;
    if (idx < KDES * HH) {
        int k = idx >> 6, n = idx & 63;
        float s = desg[n] * rsqrtf(desv[n] + BNEPS);
        float w = desW[n * KDES + k] * s;
        uint32_t hp = bfpack(w, 0.f);
        float hf = __uint_as_float(hp << 16);
        uint32_t lp = bfpack(w - hf, 0.f);
        g_Bh[k * HH + n] = (unsigned short)(hp & 0xffffu);
        g_Bl[k * HH + n] = (unsigned short)(lp & 0xffffu);
    }
    if (idx < 5 * HH) {
        int k = idx >> 6, h = idx & 63;
        float s = numg[h] * rsqrtf(numv[h] + BNEPS);
        g_Wnum[k * HH + h] = numW[h * 5 + k] * s;
    }
    if (idx < 6 * HH) {
        int k = idx >> 6, h = idx & 63;
        float s = catg[h] * rsqrtf(catv[h] + BNEPS);
        g_Wcat[k * HH + h] = catW[h * 6 + k] * s;
    }
    if (idx < 2 * HH * HH) {
        int r = idx >> 12;
        int rem = idx & 4095;
        int h = rem >> 6, k = rem & 63;
        g_Wr[r][k * HH + h] = rgcnW[r * HH * HH + h * HH + k];
    }
    if (idx < HH) {
        int h = idx;
        float sd = desg[h] * rsqrtf(desv[h] + BNEPS);
        g_bdes[h] = (desb[h] - desm[h]) * sd + desbeta[h];
        float sn = numg[h] * rsqrtf(numv[h] + BNEPS);
        g_bnum[h] = (numb[h] - numm[h]) * sn + numbeta[h];
        float sc = catg[h] * rsqrtf(catv[h] + BNEPS);
        g_bcat[h] = (catb[h] - catm[h]) * sc + catbeta[h];
    }
}

// ---------------- zero counters ----------------
__global__ void zero_kernel()
{
    int idx = blockIdx.x * blockDim.x + threadIdx.x;
    if (idx < NN) { g_cnt0[idx] = 0; g_ctot[idx] = 0; }
}

// ---------------- build: bucket edges by dst ----------------
__global__ void build_kernel(const int* __restrict__ ei, const int* __restrict__ et)
{
    int e = blockIdx.x * 256 + threadIdx.x;
    if (e >= EE) return;
    int src = ei[e];
    int dst = ei[EE + e];
    int r = et[e];
    if (r == 0) atomicAdd(&g_cnt0[dst], 1);
    int slot = atomicAdd(&g_ctot[dst], 1);
    g_bucket[dst * CAP + slot] = (uint32_t)src | ((uint32_t)r << 17);
}

// ---------------- aggregate: per-dst gather-reduce, writes per-relation MEAN ----------------
// One warp per node; lane l holds feature cols {2l, 2l+1}.
__global__ __launch_bounds__(256) void aggregate_kernel()
{
    int warp = (blockIdx.x * 256 + threadIdx.x) >> 5;
    int lane = threadIdx.x & 31;
    if (warp >= NN) return;
    int node = warp;

    int tot = g_ctot[node];
    int c0 = g_cnt0[node];
    const uint32_t* bk = &g_bucket[node * CAP];
    const float2* x2 = (const float2*)g_xv;

    float2 a0 = make_float2(0.f, 0.f);
    float2 a1 = make_float2(0.f, 0.f);

    for (int i = 0; i < tot; i += 8) {
        int m = tot - i;
        uint32_t p[8];
        float2 v[8];
#pragma unroll
        for (int j = 0; j < 8; j++) if (j < m) p[j] = bk[i + j];
#pragma unroll
        for (int j = 0; j < 8; j++) if (j < m) v[j] = x2[(p[j] & 0x1FFFFu) * 32 + lane];
#pragma unroll
        for (int j = 0; j < 8; j++) if (j < m) {
            if (p[j] >> 17) { a1.x += v[j].x; a1.y += v[j].y; }
            else            { a0.x += v[j].x; a0.y += v[j].y; }
        }
    }

    int c1 = tot - c0;
    float inv0 = 1.f / (float)max(c0, 1);
    float inv1 = 1.f / (float)max(c1, 1);
    ((float2*)&g_Av[0][node * 16])[lane] = make_float2(a0.x * inv0, a0.y * inv0);
    ((float2*)&g_Av[1][node * 16])[lane] = make_float2(a1.x * inv1, a1.y * inv1);
}

// ---------------- feat: WMMA bf16x3-split GEMM, CTA tile 128x64 ----------------
#define ALD 24
#define BLD 72
#define DLD 68
#define F_OFF_AH 0u
#define F_OFF_AL 12288u
#define F_OFF_BH 24576u
#define F_OFF_BL 29184u
#define F_OFF_D  0u
#define F_OFF_TAB 34816u
#define F_SMEM_TOTAL (34816 + 3584)

__global__ __launch_bounds__(256) void feat_kernel(const float* __restrict__ des,
                                                   const float* __restrict__ num,
                                                   const float* __restrict__ cat)
{
    extern __shared__ __align__(128) char sm[];
    __nv_bfloat16* AH = (__nv_bfloat16*)(sm + F_OFF_AH);
    __nv_bfloat16* AL = (__nv_bfloat16*)(sm + F_OFF_AL);
    __nv_bfloat16* BH = (__nv_bfloat16*)(sm + F_OFF_BH);
    __nv_bfloat16* BL = (__nv_bfloat16*)(sm + F_OFF_BL);
    float* Df  = (float*)(sm + F_OFF_D);
    float* tab = (float*)(sm + F_OFF_TAB);

    int tid = threadIdx.x;
    int warp = tid >> 5;
    int wr = warp >> 1;
    int wc = warp & 1;
    int row0 = blockIdx.x * 128;

    for (int i = tid; i < 896; i += 256) {
        float v;
        if (i < 64) v = g_bdes[i];
        else if (i < 128) v = g_bnum[i - 64];
        else if (i < 192) v = g_bcat[i - 128];
        else if (i < 512) v = g_Wnum[i - 192];
        else v = g_Wcat[i - 512];
        tab[i] = v;
    }

    wmma::fragment<wmma::accumulator, 16, 16, 16, float> acc[2][2];
#pragma unroll
    for (int i = 0; i < 2; i++)
#pragma unroll
        for (int j = 0; j < 2; j++) wmma::fill_fragment(acc[i][j], 0.f);

    auto produceA = [&](int t, int b) {
        int kk = t * 16;
#pragma unroll
        for (int i = 0; i < 2; i++) {
            int u = tid + 256 * i;
            int row = u >> 2;
            int q = u & 3;
            int grow = row0 + row;
            float4 f = make_float4(0.f, 0.f, 0.f, 0.f);
            if (grow < NN) f = *(const float4*)&des[(size_t)grow * KDES + kk + q * 4];
            uint32_t h0 = bfpack(f.x, f.y);
            uint32_t h1 = bfpack(f.z, f.w);
            uint32_t l0 = bfpack(f.x - __uint_as_float(h0 << 16),
                                 f.y - __uint_as_float(h0 & 0xffff0000u));
            uint32_t l1 = bfpack(f.z - __uint_as_float(h1 << 16),
                                 f.w - __uint_as_float(h1 & 0xffff0000u));
            int eoff = (b * 128 + row) * ALD + q * 4;
            *(uint2*)&AH[eoff] = make_uint2(h0, h1);
            *(uint2*)&AL[eoff] = make_uint2(l0, l1);
        }
    };
    auto copyB = [&](int t, int b) {
        int i = tid * 4;
        int r = i >> 6, c = i & 63;
        uint2 vh = *(const uint2*)&g_Bh[(t * 16 + r) * HH + c];
        uint2 vl = *(const uint2*)&g_Bl[(t * 16 + r) * HH + c];
        int eoff = (b * 16 + r) * BLD + c;
        *(uint2*)&BH[eoff] = vh;
        *(uint2*)&BL[eoff] = vl;
    };
    auto domma = [&](int b) {
        wmma::fragment<wmma::matrix_a, 16, 16, 16, __nv_bfloat16, wmma::row_major> ah[2], al[2];
        wmma::fragment<wmma::matrix_b, 16, 16, 16, __nv_bfloat16, wmma::row_major> bh[2], bl[2];
#pragma unroll
        for (int i = 0; i < 2; i++) {
            int base = (b * 128 + wr * 32 + i * 16) * ALD;
            wmma::load_matrix_sync(ah[i], AH + base, ALD);
            wmma::load_matrix_sync(al[i], AL + base, ALD);
        }
#pragma unroll
        for (int j = 0; j < 2; j++) {
            int base = (b * 16) * BLD + wc * 32 + j * 16;
            wmma::load_matrix_sync(bh[j], BH + base, BLD);
            wmma::load_matrix_sync(bl[j], BL + base, BLD);
        }
#pragma unroll
        for (int i = 0; i < 2; i++)
#pragma unroll
            for (int j = 0; j < 2; j++) {
                wmma::mma_sync(acc[i][j], ah[i], bh[j], acc[i][j]);
                wmma::mma_sync(acc[i][j], ah[i], bl[j], acc[i][j]);
                wmma::mma_sync(acc[i][j], al[i], bh[j], acc[i][j]);
            }
    };

    produceA(0, 0);
    copyB(0, 0);
    __syncthreads();

    const int T = KDES / 16;
    for (int t = 0; t < T; t++) {
        int b = t & 1;
        if (t + 1 < T) { produceA(t + 1, 1 - b); copyB(t + 1, 1 - b); }
        domma(b);
        __syncthreads();
    }

#pragma unroll
    for (int i = 0; i < 2; i++)
#pragma unroll
        for (int j = 0; j < 2; j++)
            wmma::store_matrix_sync(Df + (wr * 32 + i * 16) * DLD + wc * 32 + j * 16,
                                    acc[i][j], DLD, wmma::mem_row_major);
    __syncthreads();

    {
        int row = tid >> 1;
        int ch = (tid & 1) * 8;
        int grow = row0 + row;
        if (grow < NN) {
            float nb[5], cb[6];
#pragma unroll
            for (int j = 0; j < 5; j++) nb[j] = num[grow * 5 + j];
#pragma unroll
            for (int j = 0; j < 6; j++) cb[j] = cat[grow * 6 + j];
            const float4* bd4 = (const float4*)tab;
            const float4* bn4 = (const float4*)(tab + 64);
            const float4* bc4 = (const float4*)(tab + 128);
#pragma unroll
            for (int cq = 0; cq < 8; cq++) {
                int cqq = ch + cq;
                float4 d = *(const float4*)&Df[row * DLD + cqq * 4];
                float4 bd = bd4[cqq];
                float4 bn = bn4[cqq];
                float4 bc = bc4[cqq];
                float vn[4] = {bn.x, bn.y, bn.z, bn.w};
                float vc[4] = {bc.x, bc.y, bc.z, bc.w};
#pragma unroll
                for (int j = 0; j < 5; j++) {
                    float4 w = ((const float4*)(tab + 192 + j * 64))[cqq];
                    vn[0] += nb[j] * w.x; vn[1] += nb[j] * w.y;
                    vn[2] += nb[j] * w.z; vn[3] += nb[j] * w.w;
                }
#pragma unroll
                for (int j = 0; j < 6; j++) {
                    float4 w = ((const float4*)(tab + 512 + j * 64))[cqq];
                    vc[0] += cb[j] * w.x; vc[1] += cb[j] * w.y;
                    vc[2] += cb[j] * w.z; vc[3] += cb[j] * w.w;
                }
                float4 res;
                res.x = leaky(d.x + bd.x) + leaky(vn[0]) + leaky(vc[0]);
                res.y = leaky(d.y + bd.y) + leaky(vn[1]) + leaky(vc[1]);
                res.z = leaky(d.z + bd.z) + leaky(vn[2]) + leaky(vc[2]);
                res.w = leaky(d.w + bd.w) + leaky(vn[3]) + leaky(vc[3]);
                g_xv[grow * 16 + cqq] = res;
            }
        }
    }
}

// ---------------- finalA: Z = leaky(([M0;M1] @ [W0;W1]) * 0.5), K=128, single acc ----------------
__global__ __launch_bounds__(256) void finalA_kernel()
{
    __shared__ float As[2][16][132];
    __shared__ float Bs[2][16][64];
    int tid = threadIdx.x;
    int tx = tid & 15;
    int ty = tid >> 4;
    int row0 = blockIdx.x * 128;
    int c0 = tx * 4;
    int rl = ty * 8;

    int r0 = tid >> 2, kq0 = tid & 3;
    int r1 = (tid + 256) >> 2;
    int kb = tid >> 4, cb = (tid & 15) * 4;

    ull acc[4][4];
#pragma unroll
    for (int j = 0; j < 4; j++)
#pragma unroll
        for (int i = 0; i < 4; i++) acc[j][i] = 0ull;

    const float* Wflat = (const float*)g_Wr;   // [128][64] k-major concat

    float4 pA0, pA1, pB;
    auto gload = [&](int kk) {
        int kcat = kk + kq0 * 4;
        int rel = kcat >> 6;
        int offq = (kcat & 63) >> 2;
        int g0 = row0 + r0, g1 = row0 + r1;
        pA0 = (g0 < NN) ? g_Av[rel][g0 * 16 + offq] : make_float4(0.f, 0.f, 0.f, 0.f);
        pA1 = (g1 < NN) ? g_Av[rel][g1 * 16 + offq] : make_float4(0.f, 0.f, 0.f, 0.f);
        pB = *(const float4*)&Wflat[(kk + kb) * HH + cb];
    };
    auto sstore = [&](int buf) {
        As[buf][kq0 * 4 + 0][r0] = pA0.x;
        As[buf][kq0 * 4 + 1][r0] = pA0.y;
        As[buf][kq0 * 4 + 2][r0] = pA0.z;
        As[buf][kq0 * 4 + 3][r0] = pA0.w;
        As[buf][kq0 * 4 + 0][r1] = pA1.x;
        As[buf][kq0 * 4 + 1][r1] = pA1.y;
        As[buf][kq0 * 4 + 2][r1] = pA1.z;
        As[buf][kq0 * 4 + 3][r1] = pA1.w;
        *(float4*)&Bs[buf][kb][cb] = pB;
    };

    gload(0);
    sstore(0);
    __syncthreads();

#pragma unroll
    for (int t = 0; t < 8; t++) {
        int buf = t & 1;
        if (t + 1 < 8) gload((t + 1) * 16);
#pragma unroll
        for (int k = 0; k < 16; k++) {
            float4 b4 = *(const float4*)&Bs[buf][k][c0];
            ull bd0 = dupf(b4.x), bd1 = dupf(b4.y), bd2 = dupf(b4.z), bd3 = dupf(b4.w);
            ulonglong2 a01 = *(const ulonglong2*)&As[buf][k][rl];
            ulonglong2 a23 = *(const ulonglong2*)&As[buf][k][rl + 4];
            fma2(acc[0][0], a01.x, bd0); fma2(acc[0][1], a01.x, bd1);
            fma2(acc[0][2], a01.x, bd2); fma2(acc[0][3], a01.x, bd3);
            fma2(acc[1][0], a01.y, bd0); fma2(acc[1][1], a01.y, bd1);
            fma2(acc[1][2], a01.y, bd2); fma2(acc[1][3], a01.y, bd3);
            fma2(acc[2][0], a23.x, bd0); fma2(acc[2][1], a23.x, bd1);
            fma2(acc[2][2], a23.x, bd2); fma2(acc[2][3], a23.x, bd3);
            fma2(acc[3][0], a23.y, bd0); fma2(acc[3][1], a23.y, bd1);
            fma2(acc[3][2], a23.y, bd2); fma2(acc[3][3], a23.y, bd3);
        }
        if (t + 1 < 8) sstore((t + 1) & 1);
        __syncthreads();
    }

#pragma unroll
    for (int j = 0; j < 8; j++) {
        int grow = row0 + rl + j;
        if (grow < NN) {
            int jp = j >> 1, hi = j & 1;
            float res[4];
#pragma unroll
            for (int i = 0; i < 4; i++) {
                float2 u = unpk(acc[jp][i]);
                float v = hi ? u.y : u.x;
                res[i] = leaky(v * 0.5f);
            }
            g_xv[grow * 16 + tx] = make_float4(res[0], res[1], res[2], res[3]);
        }
    }
}

// ---------------- finalB: classifier, one thread per node ----------------
__global__ __launch_bounds__(256) void finalB_kernel(const float* __restrict__ W1,
                                                     const float* __restrict__ b1,
                                                     const float* __restrict__ W2,
                                                     const float* __restrict__ b2,
                                                     float* __restrict__ out)
{
    __shared__ ull   C1p[64][16];
    __shared__ float C2s[64];
    __shared__ float B1s[32];

    int tid = threadIdx.x;
    for (int idx = tid; idx < 1024; idx += 256) {
        int k = idx >> 4, p = idx & 15;
        C1p[k][p] = pk2(W1[(2 * p) * 64 + k], W1[(2 * p + 1) * 64 + k]);
    }
    if (tid < 64) C2s[tid] = W2[tid];
    if (tid < 32) B1s[tid] = b1[tid];
    __syncthreads();

    int n = blockIdx.x * 256 + tid;
    if (n >= NN) return;

    ull hacc[16];
#pragma unroll
    for (int p = 0; p < 16; p++) hacc[p] = 0ull;

    for (int kq = 0; kq < 16; kq++) {
        float4 z4 = g_xv[n * 16 + kq];
        float zc[4] = {z4.x, z4.y, z4.z, z4.w};
#pragma unroll
        for (int c = 0; c < 4; c++) {
            int k = kq * 4 + c;
            ull zd = dupf(zc[c]);
            const ulonglong2* wv = (const ulonglong2*)&C1p[k][0];
#pragma unroll
            for (int p2 = 0; p2 < 8; p2++) {
                ulonglong2 w = wv[p2];
                fma2(hacc[2 * p2 + 0], zd, w.x);
                fma2(hacc[2 * p2 + 1], zd, w.y);
            }
        }
    }

    float q0 = 0.f, q1 = 0.f;
#pragma unroll
    for (int p = 0; p < 16; p++) {
        float2 u = unpk(hacc[p]);
        float h0 = leaky(u.x + B1s[2 * p]);
        float h1 = leaky(u.y + B1s[2 * p + 1]);
        q0 += h0 * C2s[2 * p] + h1 * C2s[2 * p + 1];
        q1 += h0 * C2s[32 + 2 * p] + h1 * C2s[32 + 2 * p + 1];
    }
    out[n * 2 + 0] = q0 + b2[0];
    out[n * 2 + 1] = q1 + b2[1];
}

// ---------------- launch ----------------
extern "C" void kernel_launch(void* const* d_in, const int* in_sizes, int n_in,
                              void* d_out, int out_size)
{
    const float* des     = (const float*)d_in[0];
    const float* num     = (const float*)d_in[1];
    const float* cat     = (const float*)d_in[2];
    const int*   ei      = (const int*)d_in[3];
    const int*   et      = (const int*)d_in[4];
    const float* desW    = (const float*)d_in[5];
    const float* desb    = (const float*)d_in[6];
    const float* numW    = (const float*)d_in[7];
    const float* numb    = (const float*)d_in[8];
    const float* catW    = (const float*)d_in[9];
    const float* catb    = (const float*)d_in[10];
    const float* desg    = (const float*)d_in[11];
    const float* desbeta = (const float*)d_in[12];
    const float* desm    = (const float*)d_in[13];
    const float* desv    = (const float*)d_in[14];
    const float* numg    = (const float*)d_in[15];
    const float* numbeta = (const float*)d_in[16];
    const float* numm    = (const float*)d_in[17];
    const float* numv    = (const float*)d_in[18];
    const float* catg    = (const float*)d_in[19];
    const float* catbeta = (const float*)d_in[20];
    const float* catm    = (const float*)d_in[21];
    const float* catv    = (const float*)d_in[22];
    const float* rgcnW   = (const float*)d_in[23];
    const float* clsW1   = (const float*)d_in[24];
    const float* clsb1   = (const float*)d_in[25];
    const float* clsW2   = (const float*)d_in[26];
    const float* clsb2   = (const float*)d_in[27];
    float* out = (float*)d_out;

    prep_kernel<<<(KDES * HH + 255) / 256, 256>>>(
        desW, desb, numW, numb, catW, catb,
        desg, desbeta, desm, desv,
        numg, numbeta, numm, numv,
        catg, catbeta, catm, catv,
        rgcnW);

    zero_kernel<<<(NN + 255) / 256, 256>>>();

    build_kernel<<<(EE + 255) / 256, 256>>>(ei, et);

    feat_kernel<<<(NN + 127) / 128, 256, F_SMEM_TOTAL>>>(des, num, cat);

    aggregate_kernel<<<(NN * 32 + 255) / 256, 256>>>();

    finalA_kernel<<<(NN + 127) / 128, 256>>>();

    finalB_kernel<<<(NN + 255) / 256, 256>>>(clsW1, clsb1, clsW2, clsb2, out);
}

// round 7
// speedup vs baseline: 3.9092x; 1.0206x over previous
#include <cuda_runtime.h>
#include <cuda_bf16.h>
#include <mma.h>
#include <cstdint>

using namespace nvcuda;

#define NN   100000
#define EE   3200000
#define HH   64
#define KDES 768
#define RNEG 0.01f
#define BNEPS 1e-5f
#define CAP  96

typedef unsigned long long ull;

// ---------------- scratch (static __device__ globals; no allocation) ----------------
__device__ float4 g_xv[NN * 16];          // node features x [N,64]; later reused for Z
__device__ float4 g_Av[2][NN * 16];       // per-relation MEAN vectors [N,64]
__device__ int    g_cnt0[NN];             // relation-0 in-degree
__device__ int    g_ctot[NN];             // total in-degree (cursor during build)
__device__ uint32_t g_bucket[NN * CAP];   // per-dst edge payloads: src | rel<<17
__device__ float  g_bdes[HH];
__device__ float  g_Wnum[5 * HH];
__device__ float  g_bnum[HH];
__device__ float  g_Wcat[6 * HH];
__device__ float  g_bcat[HH];
__device__ float  g_Wr[2][HH * HH];       // rgcn weights, k-major (contiguous = [128][64])
// bf16-split BN-folded des weight, k-major [768][64]
__device__ unsigned short g_Bh[KDES * HH];
__device__ unsigned short g_Bl[KDES * HH];

__device__ __forceinline__ float leaky(float v) { return v > 0.f ? v : RNEG * v; }

// packed f32x2 helpers
__device__ __forceinline__ void fma2(ull& d, ull a, ull b) {
    asm("fma.rn.f32x2 %0, %1, %2, %0;" : "+l"(d) : "l"(a), "l"(b));
}
__device__ __forceinline__ ull dupf(float x) {
    ull r; asm("mov.b64 %0, {%1, %1};" : "=l"(r) : "f"(x)); return r;
}
__device__ __forceinline__ ull pk2(float a, float b) {
    ull r; asm("mov.b64 %0, {%1, %2};" : "=l"(r) : "f"(a), "f"(b)); return r;
}
__device__ __forceinline__ float2 unpk(ull v) {
    float2 r; asm("mov.b64 {%0, %1}, %2;" : "=f"(r.x), "=f"(r.y) : "l"(v)); return r;
}
__device__ __forceinline__ uint32_t bfpack(float lo, float hi) {
    uint32_t r;
    asm("cvt.rn.bf16x2.f32 %0, %1, %2;" : "=r"(r) : "f"(hi), "f"(lo));
    return r;
}

// ---------------- prep ----------------
__global__ void prep_kernel(const float* __restrict__ desW, const float* __restrict__ desb,
                            const float* __restrict__ numW, const float* __restrict__ numb,
                            const float* __restrict__ catW, const float* __restrict__ catb,
                            const float* __restrict__ desg, const float* __restrict__ desbeta,
                            const float* __restrict__ desm, const float* __restrict__ desv,
                            const float* __restrict__ numg, const float* __restrict__ numbeta,
                            const float* __restrict__ numm, const float* __restrict__ numv,
                            const float* __restrict__ catg, const float* __restrict__ catbeta,
                            const float* __restrict__ catm, const float* __restrict__ catv,
                            const float* __restrict__ rgcnW)
{
    int idx = blockIdx.x * blockDim.x + threadIdx.x;
    if (idx < KDES * HH) {
        int k = idx >> 6, n = idx & 63;
        float s = desg[n] * rsqrtf(desv[n] + BNEPS);
        float w = desW[n * KDES + k] * s;
        uint32_t hp = bfpack(w, 0.f);
        float hf = __uint_as_float(hp << 16);
        uint32_t lp = bfpack(w - hf, 0.f);
        g_Bh[k * HH + n] = (unsigned short)(hp & 0xffffu);
        g_Bl[k * HH + n] = (unsigned short)(lp & 0xffffu);
    }
    if (idx < 5 * HH) {
        int k = idx >> 6, h = idx & 63;
        float s = numg[h] * rsqrtf(numv[h] + BNEPS);
        g_Wnum[k * HH + h] = numW[h * 5 + k] * s;
    }
    if (idx < 6 * HH) {
        int k = idx >> 6, h = idx & 63;
        float s = catg[h] * rsqrtf(catv[h] + BNEPS);
        g_Wcat[k * HH + h] = catW[h * 6 + k] * s;
    }
    if (idx < 2 * HH * HH) {
        int r = idx >> 12;
        int rem = idx & 4095;
        int h = rem >> 6, k = rem & 63;
        g_Wr[r][k * HH + h] = rgcnW[r * HH * HH + h * HH + k];
    }
    if (idx < HH) {
        int h = idx;
        float sd = desg[h] * rsqrtf(desv[h] + BNEPS);
        g_bdes[h] = (desb[h] - desm[h]) * sd + desbeta[h];
        float sn = numg[h] * rsqrtf(numv[h] + BNEPS);
        g_bnum[h] = (numb[h] - numm[h]) * sn + numbeta[h];
        float sc = catg[h] * rsqrtf(catv[h] + BNEPS);
        g_bcat[h] = (catb[h] - catm[h]) * sc + catbeta[h];
    }
}

// ---------------- zero counters ----------------
__global__ void zero_kernel()
{
    int idx = blockIdx.x * blockDim.x + threadIdx.x;
    if (idx < NN) { g_cnt0[idx] = 0; g_ctot[idx] = 0; }
}

// ---------------- build: bucket edges by dst ----------------
__global__ void build_kernel(const int* __restrict__ ei, const int* __restrict__ et)
{
    int e = blockIdx.x * 256 + threadIdx.x;
    if (e >= EE) return;
    int src = ei[e];
    int dst = ei[EE + e];
    int r = et[e];
    if (r == 0) atomicAdd(&g_cnt0[dst], 1);
    int slot = atomicAdd(&g_ctot[dst], 1);
    g_bucket[dst * CAP + slot] = (uint32_t)src | ((uint32_t)r << 17);
}

// ---------------- aggregate: per-dst gather-reduce, writes per-relation MEAN ----------------
__global__ __launch_bounds__(256) void aggregate_kernel()
{
    int warp = (blockIdx.x * 256 + threadIdx.x) >> 5;
    int lane = threadIdx.x & 31;
    if (warp >= NN) return;
    int node = warp;

    int tot = g_ctot[node];
    int c0 = g_cnt0[node];
    const uint32_t* bk = &g_bucket[node * CAP];
    const float2* x2 = (const float2*)g_xv;

    float2 a0 = make_float2(0.f, 0.f);
    float2 a1 = make_float2(0.f, 0.f);

    for (int i = 0; i < tot; i += 8) {
        int m = tot - i;
        uint32_t p[8];
        float2 v[8];
#pragma unroll
        for (int j = 0; j < 8; j++) if (j < m) p[j] = bk[i + j];
#pragma unroll
        for (int j = 0; j < 8; j++) if (j < m) v[j] = x2[(p[j] & 0x1FFFFu) * 32 + lane];
#pragma unroll
        for (int j = 0; j < 8; j++) if (j < m) {
            if (p[j] >> 17) { a1.x += v[j].x; a1.y += v[j].y; }
            else            { a0.x += v[j].x; a0.y += v[j].y; }
        }
    }

    int c1 = tot - c0;
    float inv0 = 1.f / (float)max(c0, 1);
    float inv1 = 1.f / (float)max(c1, 1);
    ((float2*)&g_Av[0][node * 16])[lane] = make_float2(a0.x * inv0, a0.y * inv0);
    ((float2*)&g_Av[1][node * 16])[lane] = make_float2(a1.x * inv1, a1.y * inv1);
}

// ---------------- feat: WMMA bf16x3-split GEMM, CTA tile 128x64, BK=32, early-load pipeline ----------------
// dynamic smem (bytes):
//   AH @ 0      : [2][128][40] bf16 = 20480
//   AL @ 20480  : [2][128][40] bf16 = 20480
//   BH @ 40960  : [2][32][72]  bf16 = 9216
//   BL @ 50176  : [2][32][72]  bf16 = 9216   (A/B end at 59392)
//   D  @ 0      : [128][68] f32 = 34816      (overlaps A; used only after last MMA)
//   TAB@ 59392  : 896 floats = 3584
#define ALD 40
#define BLD 72
#define DLD 68
#define F_OFF_AH 0u
#define F_OFF_AL 20480u
#define F_OFF_BH 40960u
#define F_OFF_BL 50176u
#define F_OFF_D  0u
#define F_OFF_TAB 59392u
#define F_SMEM_TOTAL (59392 + 3584)

__global__ __launch_bounds__(256) void feat_kernel(const float* __restrict__ des,
                                                   const float* __restrict__ num,
                                                   const float* __restrict__ cat)
{
    extern __shared__ __align__(128) char sm[];
    __nv_bfloat16* AH = (__nv_bfloat16*)(sm + F_OFF_AH);
    __nv_bfloat16* AL = (__nv_bfloat16*)(sm + F_OFF_AL);
    __nv_bfloat16* BH = (__nv_bfloat16*)(sm + F_OFF_BH);
    __nv_bfloat16* BL = (__nv_bfloat16*)(sm + F_OFF_BL);
    float* Df  = (float*)(sm + F_OFF_D);
    float* tab = (float*)(sm + F_OFF_TAB);

    int tid = threadIdx.x;
    int warp = tid >> 5;
    int wr = warp >> 1;
    int wc = warp & 1;
    int row0 = blockIdx.x * 128;

    // thread's A-load geometry: 4 float4 slots, row = slot>>3, q = slot&7
    int arow[4], aq[4];
#pragma unroll
    for (int i = 0; i < 4; i++) {
        int u = tid + 256 * i;
        arow[i] = u >> 3;
        aq[i] = u & 7;
    }

    for (int i = tid; i < 896; i += 256) {
        float v;
        if (i < 64) v = g_bdes[i];
        else if (i < 128) v = g_bnum[i - 64];
        else if (i < 192) v = g_bcat[i - 128];
        else if (i < 512) v = g_Wnum[i - 192];
        else v = g_Wcat[i - 512];
        tab[i] = v;
    }

    wmma::fragment<wmma::accumulator, 16, 16, 16, float> acc[2][2];
#pragma unroll
    for (int i = 0; i < 2; i++)
#pragma unroll
        for (int j = 0; j < 2; j++) wmma::fill_fragment(acc[i][j], 0.f);

    float4 fA[4];
    uint2 fBh[2], fBl[2];

    auto gload = [&](int t) {
        int kk = t * 32;
#pragma unroll
        for (int i = 0; i < 4; i++) {
            int grow = row0 + arow[i];
            fA[i] = (grow < NN) ? *(const float4*)&des[(size_t)grow * KDES + kk + aq[i] * 4]
                                : make_float4(0.f, 0.f, 0.f, 0.f);
        }
#pragma unroll
        for (int s = 0; s < 2; s++) {
            int i4 = (tid + 256 * s) * 4;
            int r = i4 >> 6, c = i4 & 63;
            fBh[s] = *(const uint2*)&g_Bh[(t * 32 + r) * HH + c];
            fBl[s] = *(const uint2*)&g_Bl[(t * 32 + r) * HH + c];
        }
    };
    auto sstore = [&](int b) {
#pragma unroll
        for (int i = 0; i < 4; i++) {
            float4 f = fA[i];
            uint32_t h0 = bfpack(f.x, f.y);
            uint32_t h1 = bfpack(f.z, f.w);
            uint32_t l0 = bfpack(f.x - __uint_as_float(h0 << 16),
                                 f.y - __uint_as_float(h0 & 0xffff0000u));
            uint32_t l1 = bfpack(f.z - __uint_as_float(h1 << 16),
                                 f.w - __uint_as_float(h1 & 0xffff0000u));
            int eoff = (b * 128 + arow[i]) * ALD + aq[i] * 4;
            *(uint2*)&AH[eoff] = make_uint2(h0, h1);
            *(uint2*)&AL[eoff] = make_uint2(l0, l1);
        }
#pragma unroll
        for (int s = 0; s < 2; s++) {
            int i4 = (tid + 256 * s) * 4;
            int r = i4 >> 6, c = i4 & 63;
            int eoff = (b * 32 + r) * BLD + c;
            *(uint2*)&BH[eoff] = fBh[s];
            *(uint2*)&BL[eoff] = fBl[s];
        }
    };
    auto domma = [&](int b) {
#pragma unroll
        for (int kc = 0; kc < 2; kc++) {
            wmma::fragment<wmma::matrix_a, 16, 16, 16, __nv_bfloat16, wmma::row_major> ah[2], al[2];
            wmma::fragment<wmma::matrix_b, 16, 16, 16, __nv_bfloat16, wmma::row_major> bh[2], bl[2];
#pragma unroll
            for (int i = 0; i < 2; i++) {
                int base = (b * 128 + wr * 32 + i * 16) * ALD + kc * 16;
                wmma::load_matrix_sync(ah[i], AH + base, ALD);
                wmma::load_matrix_sync(al[i], AL + base, ALD);
            }
#pragma unroll
            for (int j = 0; j < 2; j++) {
                int base = (b * 32 + kc * 16) * BLD + wc * 32 + j * 16;
                wmma::load_matrix_sync(bh[j], BH + base, BLD);
                wmma::load_matrix_sync(bl[j], BL + base, BLD);
            }
#pragma unroll
            for (int i = 0; i < 2; i++)
#pragma unroll
                for (int j = 0; j < 2; j++) {
                    wmma::mma_sync(acc[i][j], ah[i], bh[j], acc[i][j]);
                    wmma::mma_sync(acc[i][j], ah[i], bl[j], acc[i][j]);
                    wmma::mma_sync(acc[i][j], al[i], bh[j], acc[i][j]);
                }
        }
    };

    gload(0);
    sstore(0);
    __syncthreads();

    const int T = KDES / 32;   // 24
    for (int t = 0; t < T; t++) {
        int b = t & 1;
        if (t + 1 < T) gload(t + 1);      // loads in flight during MMA
        domma(b);
        if (t + 1 < T) sstore(1 - b);     // convert + store after compute
        __syncthreads();
    }

#pragma unroll
    for (int i = 0; i < 2; i++)
#pragma unroll
        for (int j = 0; j < 2; j++)
            wmma::store_matrix_sync(Df + (wr * 32 + i * 16) * DLD + wc * 32 + j * 16,
                                    acc[i][j], DLD, wmma::mem_row_major);
    __syncthreads();

    {
        int row = tid >> 1;
        int ch = (tid & 1) * 8;
        int grow = row0 + row;
        if (grow < NN) {
            float nb[5], cb[6];
#pragma unroll
            for (int j = 0; j < 5; j++) nb[j] = num[grow * 5 + j];
#pragma unroll
            for (int j = 0; j < 6; j++) cb[j] = cat[grow * 6 + j];
            const float4* bd4 = (const float4*)tab;
            const float4* bn4 = (const float4*)(tab + 64);
            const float4* bc4 = (const float4*)(tab + 128);
#pragma unroll
            for (int cq = 0; cq < 8; cq++) {
                int cqq = ch + cq;
                float4 d = *(const float4*)&Df[row * DLD + cqq * 4];
                float4 bd = bd4[cqq];
                float4 bn = bn4[cqq];
                float4 bc = bc4[cqq];
                float vn[4] = {bn.x, bn.y, bn.z, bn.w};
                float vc[4] = {bc.x, bc.y, bc.z, bc.w};
#pragma unroll
                for (int j = 0; j < 5; j++) {
                    float4 w = ((const float4*)(tab + 192 + j * 64))[cqq];
                    vn[0] += nb[j] * w.x; vn[1] += nb[j] * w.y;
                    vn[2] += nb[j] * w.z; vn[3] += nb[j] * w.w;
                }
#pragma unroll
                for (int j = 0; j < 6; j++) {
                    float4 w = ((const float4*)(tab + 512 + j * 64))[cqq];
                    vc[0] += cb[j] * w.x; vc[1] += cb[j] * w.y;
                    vc[2] += cb[j] * w.z; vc[3] += cb[j] * w.w;
                }
                float4 res;
                res.x = leaky(d.x + bd.x) + leaky(vn[0]) + leaky(vc[0]);
                res.y = leaky(d.y + bd.y) + leaky(vn[1]) + leaky(vc[1]);
                res.z = leaky(d.z + bd.z) + leaky(vn[2]) + leaky(vc[2]);
                res.w = leaky(d.w + bd.w) + leaky(vn[3]) + leaky(vc[3]);
                g_xv[grow * 16 + cqq] = res;
            }
        }
    }
}

// ---------------- finalA: Z = leaky(([M0;M1] @ [W0;W1]) * 0.5), K=128, single acc ----------------
__global__ __launch_bounds__(256) void finalA_kernel()
{
    __shared__ float As[2][16][132];
    __shared__ float Bs[2][16][64];
    int tid = threadIdx.x;
    int tx = tid & 15;
    int ty = tid >> 4;
    int row0 = blockIdx.x * 128;
    int c0 = tx * 4;
    int rl = ty * 8;

    int r0 = tid >> 2, kq0 = tid & 3;
    int r1 = (tid + 256) >> 2;
    int kb = tid >> 4, cb = (tid & 15) * 4;

    ull acc[4][4];
#pragma unroll
    for (int j = 0; j < 4; j++)
#pragma unroll
        for (int i = 0; i < 4; i++) acc[j][i] = 0ull;

    const float* Wflat = (const float*)g_Wr;

    float4 pA0, pA1, pB;
    auto gload = [&](int kk) {
        int kcat = kk + kq0 * 4;
        int rel = kcat >> 6;
        int offq = (kcat & 63) >> 2;
        int g0 = row0 + r0, g1 = row0 + r1;
        pA0 = (g0 < NN) ? g_Av[rel][g0 * 16 + offq] : make_float4(0.f, 0.f, 0.f, 0.f);
        pA1 = (g1 < NN) ? g_Av[rel][g1 * 16 + offq] : make_float4(0.f, 0.f, 0.f, 0.f);
        pB = *(const float4*)&Wflat[(kk + kb) * HH + cb];
    };
    auto sstore = [&](int buf) {
        As[buf][kq0 * 4 + 0][r0] = pA0.x;
        As[buf][kq0 * 4 + 1][r0] = pA0.y;
        As[buf][kq0 * 4 + 2][r0] = pA0.z;
        As[buf][kq0 * 4 + 3][r0] = pA0.w;
        As[buf][kq0 * 4 + 0][r1] = pA1.x;
        As[buf][kq0 * 4 + 1][r1] = pA1.y;
        As[buf][kq0 * 4 + 2][r1] = pA1.z;
        As[buf][kq0 * 4 + 3][r1] = pA1.w;
        *(float4*)&Bs[buf][kb][cb] = pB;
    };

    gload(0);
    sstore(0);
    __syncthreads();

#pragma unroll
    for (int t = 0; t < 8; t++) {
        int buf = t & 1;
        if (t + 1 < 8) gload((t + 1) * 16);
#pragma unroll
        for (int k = 0; k < 16; k++) {
            float4 b4 = *(const float4*)&Bs[buf][k][c0];
            ull bd0 = dupf(b4.x), bd1 = dupf(b4.y), bd2 = dupf(b4.z), bd3 = dupf(b4.w);
            ulonglong2 a01 = *(const ulonglong2*)&As[buf][k][rl];
            ulonglong2 a23 = *(const ulonglong2*)&As[buf][k][rl + 4];
            fma2(acc[0][0], a01.x, bd0); fma2(acc[0][1], a01.x, bd1);
            fma2(acc[0][2], a01.x, bd2); fma2(acc[0][3], a01.x, bd3);
            fma2(acc[1][0], a01.y, bd0); fma2(acc[1][1], a01.y, bd1);
            fma2(acc[1][2], a01.y, bd2); fma2(acc[1][3], a01.y, bd3);
            fma2(acc[2][0], a23.x, bd0); fma2(acc[2][1], a23.x, bd1);
            fma2(acc[2][2], a23.x, bd2); fma2(acc[2][3], a23.x, bd3);
            fma2(acc[3][0], a23.y, bd0); fma2(acc[3][1], a23.y, bd1);
            fma2(acc[3][2], a23.y, bd2); fma2(acc[3][3], a23.y, bd3);
        }
        if (t + 1 < 8) sstore((t + 1) & 1);
        __syncthreads();
    }

#pragma unroll
    for (int j = 0; j < 8; j++) {
        int grow = row0 + rl + j;
        if (grow < NN) {
            int jp = j >> 1, hi = j & 1;
            float res[4];
#pragma unroll
            for (int i = 0; i < 4; i++) {
                float2 u = unpk(acc[jp][i]);
                float v = hi ? u.y : u.x;
                res[i] = leaky(v * 0.5f);
            }
            g_xv[grow * 16 + tx] = make_float4(res[0], res[1], res[2], res[3]);
        }
    }
}

// ---------------- finalB: classifier, one thread per node ----------------
__global__ __launch_bounds__(256) void finalB_kernel(const float* __restrict__ W1,
                                                     const float* __restrict__ b1,
                                                     const float* __restrict__ W2,
                                                     const float* __restrict__ b2,
                                                     float* __restrict__ out)
{
    __shared__ ull   C1p[64][16];
    __shared__ float C2s[64];
    __shared__ float B1s[32];

    int tid = threadIdx.x;
    for (int idx = tid; idx < 1024; idx += 256) {
        int k = idx >> 4, p = idx & 15;
        C1p[k][p] = pk2(W1[(2 * p) * 64 + k], W1[(2 * p + 1) * 64 + k]);
    }
    if (tid < 64) C2s[tid] = W2[tid];
    if (tid < 32) B1s[tid] = b1[tid];
    __syncthreads();

    int n = blockIdx.x * 256 + tid;
    if (n >= NN) return;

    ull hacc[16];
#pragma unroll
    for (int p = 0; p < 16; p++) hacc[p] = 0ull;

    for (int kq = 0; kq < 16; kq++) {
        float4 z4 = g_xv[n * 16 + kq];
        float zc[4] = {z4.x, z4.y, z4.z, z4.w};
#pragma unroll
        for (int c = 0; c < 4; c++) {
            int k = kq * 4 + c;
            ull zd = dupf(zc[c]);
            const ulonglong2* wv = (const ulonglong2*)&C1p[k][0];
#pragma unroll
            for (int p2 = 0; p2 < 8; p2++) {
                ulonglong2 w = wv[p2];
                fma2(hacc[2 * p2 + 0], zd, w.x);
                fma2(hacc[2 * p2 + 1], zd, w.y);
            }
        }
    }

    float q0 = 0.f, q1 = 0.f;
#pragma unroll
    for (int p = 0; p < 16; p++) {
        float2 u = unpk(hacc[p]);
        float h0 = leaky(u.x + B1s[2 * p]);
        float h1 = leaky(u.y + B1s[2 * p + 1]);
        q0 += h0 * C2s[2 * p] + h1 * C2s[2 * p + 1];
        q1 += h0 * C2s[32 + 2 * p] + h1 * C2s[32 + 2 * p + 1];
    }
    out[n * 2 + 0] = q0 + b2[0];
    out[n * 2 + 1] = q1 + b2[1];
}

// ---------------- launch ----------------
extern "C" void kernel_launch(void* const* d_in, const int* in_sizes, int n_in,
                              void* d_out, int out_size)
{
    const float* des     = (const float*)d_in[0];
    const float* num     = (const float*)d_in[1];
    const float* cat     = (const float*)d_in[2];
    const int*   ei      = (const int*)d_in[3];
    const int*   et      = (const int*)d_in[4];
    const float* desW    = (const float*)d_in[5];
    const float* desb    = (const float*)d_in[6];
    const float* numW    = (const float*)d_in[7];
    const float* numb    = (const float*)d_in[8];
    const float* catW    = (const float*)d_in[9];
    const float* catb    = (const float*)d_in[10];
    const float* desg    = (const float*)d_in[11];
    const float* desbeta = (const float*)d_in[12];
    const float* desm    = (const float*)d_in[13];
    const float* desv    = (const float*)d_in[14];
    const float* numg    = (const float*)d_in[15];
    const float* numbeta = (const float*)d_in[16];
    const float* numm    = (const float*)d_in[17];
    const float* numv    = (const float*)d_in[18];
    const float* catg    = (const float*)d_in[19];
    const float* catbeta = (const float*)d_in[20];
    const float* catm    = (const float*)d_in[21];
    const float* catv    = (const float*)d_in[22];
    const float* rgcnW   = (const float*)d_in[23];
    const float* clsW1   = (const float*)d_in[24];
    const float* clsb1   = (const float*)d_in[25];
    const float* clsW2   = (const float*)d_in[26];
    const float* clsb2   = (const float*)d_in[27];
    float* out = (float*)d_out;

    cudaFuncSetAttribute(feat_kernel, cudaFuncAttributeMaxDynamicSharedMemorySize,
                         F_SMEM_TOTAL);

    prep_kernel<<<(KDES * HH + 255) / 256, 256>>>(
        desW, desb, numW, numb, catW, catb,
        desg, desbeta, desm, desv,
        numg, numbeta, numm, numv,
        catg, catbeta, catm, catv,
        rgcnW);

    zero_kernel<<<(NN + 255) / 256, 256>>>();

    build_kernel<<<(EE + 255) / 256, 256>>>(ei, et);

    feat_kernel<<<(NN + 127) / 128, 256, F_SMEM_TOTAL>>>(des, num, cat);

    aggregate_kernel<<<(NN * 32 + 255) / 256, 256>>>();

    finalA_kernel<<<(NN + 127) / 128, 256>>>();

    finalB_kernel<<<(NN + 255) / 256, 256>>>(clsW1, clsb1, clsW2, clsb2, out);
}

// round 9
// speedup vs baseline: 3.9972x; 1.0225x over previous
#include <cuda_runtime.h>
#include <cuda_bf16.h>
#include <mma.h>
#include <cstdint>

using namespace nvcuda;

#define NN   100000
#define EE   3200000
#define HH   64
#define KDES 768
#define RNEG 0.01f
#define BNEPS 1e-5f
#define CAP  96

typedef unsigned long long ull;

// ---------------- scratch (static __device__ globals; no allocation) ----------------
__device__ float4 g_xv[NN * 16];          // node features x [N,64]; later reused for Z
__device__ float4 g_Av[2][NN * 16];       // per-relation MEAN vectors [N,64]
__device__ int    g_cnt0[NN];             // relation-0 in-degree
__device__ int    g_ctot[NN];             // total in-degree (cursor during build)
__device__ uint32_t g_bucket[NN * CAP];   // per-dst edge payloads: src | rel<<17
__device__ float  g_bdes[HH];
__device__ float  g_Wnum[5 * HH];
__device__ float  g_bnum[HH];
__device__ float  g_Wcat[6 * HH];
__device__ float  g_bcat[HH];
__device__ float  g_Wr[2][HH * HH];       // rgcn weights, k-major (contiguous = [128][64])
// bf16-split BN-folded des weight, k-major [768][64]
__device__ unsigned short g_Bh[KDES * HH];
__device__ unsigned short g_Bl[KDES * HH];

__device__ __forceinline__ float leaky(float v) { return v > 0.f ? v : RNEG * v; }

// packed f32x2 helpers
__device__ __forceinline__ void fma2(ull& d, ull a, ull b) {
    asm("fma.rn.f32x2 %0, %1, %2, %0;" : "+l"(d) : "l"(a), "l"(b));
}
__device__ __forceinline__ ull dupf(float x) {
    ull r; asm("mov.b64 %0, {%1, %1};" : "=l"(r) : "f"(x)); return r;
}
__device__ __forceinline__ ull pk2(float a, float b) {
    ull r; asm("mov.b64 %0, {%1, %2};" : "=l"(r) : "f"(a), "f"(b)); return r;
}
__device__ __forceinline__ float2 unpk(ull v) {
    float2 r; asm("mov.b64 {%0, %1}, %2;" : "=f"(r.x), "=f"(r.y) : "l"(v)); return r;
}
__device__ __forceinline__ uint32_t bfpack(float lo, float hi) {
    uint32_t r;
    asm("cvt.rn.bf16x2.f32 %0, %1, %2;" : "=r"(r) : "f"(hi), "f"(lo));
    return r;
}
__device__ __forceinline__ uint32_t smem_u32(const void* p) {
    uint32_t a;
    asm("{ .reg .u64 t; cvta.to.shared.u64 t, %1; cvt.u32.u64 %0, t; }" : "=r"(a) : "l"(p));
    return a;
}
__device__ __forceinline__ void cp16(uint32_t dst, const void* src, int srcsize) {
    asm volatile("cp.async.cg.shared.global [%0], [%1], 16, %2;"
                 :: "r"(dst), "l"(src), "r"(srcsize) : "memory");
}
__device__ __forceinline__ void cp_commit() {
    asm volatile("cp.async.commit_group;" ::: "memory");
}
template<int N> __device__ __forceinline__ void cp_wait() {
    asm volatile("cp.async.wait_group %0;" :: "n"(N) : "memory");
}

// ---------------- prep ----------------
__global__ void prep_kernel(const float* __restrict__ desW, const float* __restrict__ desb,
                            const float* __restrict__ numW, const float* __restrict__ numb,
                            const float* __restrict__ catW, const float* __restrict__ catb,
                            const float* __restrict__ desg, const float* __restrict__ desbeta,
                            const float* __restrict__ desm, const float* __restrict__ desv,
                            const float* __restrict__ numg, const float* __restrict__ numbeta,
                            const float* __restrict__ numm, const float* __restrict__ numv,
                            const float* __restrict__ catg, const float* __restrict__ catbeta,
                            const float* __restrict__ catm, const float* __restrict__ catv,
                            const float* __restrict__ rgcnW)
{
    int idx = blockIdx.x * blockDim.x + threadIdx.x;
    if (idx < KDES * HH) {
        int k = idx >> 6, n = idx & 63;
        float s = desg[n] * rsqrtf(desv[n] + BNEPS);
        float w = desW[n * KDES + k] * s;
        uint32_t hp = bfpack(w, 0.f);
        float hf = __uint_as_float(hp << 16);
        uint32_t lp = bfpack(w - hf, 0.f);
        g_Bh[k * HH + n] = (unsigned short)(hp & 0xffffu);
        g_Bl[k * HH + n] = (unsigned short)(lp & 0xffffu);
    }
    if (idx < 5 * HH) {
        int k = idx >> 6, h = idx & 63;
        float s = numg[h] * rsqrtf(numv[h] + BNEPS);
        g_Wnum[k * HH + h] = numW[h * 5 + k] * s;
    }
    if (idx < 6 * HH) {
        int k = idx >> 6, h = idx & 63;
        float s = catg[h] * rsqrtf(catv[h] + BNEPS);
        g_Wcat[k * HH + h] = catW[h * 6 + k] * s;
    }
    if (idx < 2 * HH * HH) {
        int r = idx >> 12;
        int rem = idx & 4095;
        int h = rem >> 6, k = rem & 63;
        g_Wr[r][k * HH + h] = rgcnW[r * HH * HH + h * HH + k];
    }
    if (idx < HH) {
        int h = idx;
        float sd = desg[h] * rsqrtf(desv[h] + BNEPS);
        g_bdes[h] = (desb[h] - desm[h]) * sd + desbeta[h];
        float sn = numg[h] * rsqrtf(numv[h] + BNEPS);
        g_bnum[h] = (numb[h] - numm[h]) * sn + numbeta[h];
        float sc = catg[h] * rsqrtf(catv[h] + BNEPS);
        g_bcat[h] = (catb[h] - catm[h]) * sc + catbeta[h];
    }
}

// ---------------- zero counters ----------------
__global__ void zero_kernel()
{
    int idx = blockIdx.x * blockDim.x + threadIdx.x;
    if (idx < NN) { g_cnt0[idx] = 0; g_ctot[idx] = 0; }
}

// ---------------- build: bucket edges by dst ----------------
__global__ void build_kernel(const int* __restrict__ ei, const int* __restrict__ et)
{
    int e = blockIdx.x * 256 + threadIdx.x;
    if (e >= EE) return;
    int src = ei[e];
    int dst = ei[EE + e];
    int r = et[e];
    if (r == 0) atomicAdd(&g_cnt0[dst], 1);
    int slot = atomicAdd(&g_ctot[dst], 1);
    g_bucket[dst * CAP + slot] = (uint32_t)src | ((uint32_t)r << 17);
}

// ---------------- aggregate: per-dst gather-reduce, writes per-relation MEAN ----------------
__global__ __launch_bounds__(256) void aggregate_kernel()
{
    int warp = (blockIdx.x * 256 + threadIdx.x) >> 5;
    int lane = threadIdx.x & 31;
    if (warp >= NN) return;
    int node = warp;

    int tot = g_ctot[node];
    int c0 = g_cnt0[node];
    const uint32_t* bk = &g_bucket[node * CAP];
    const float2* x2 = (const float2*)g_xv;

    float2 a0 = make_float2(0.f, 0.f);
    float2 a1 = make_float2(0.f, 0.f);

    for (int i = 0; i < tot; i += 8) {
        int m = tot - i;
        uint32_t p[8];
        float2 v[8];
#pragma unroll
        for (int j = 0; j < 8; j++) if (j < m) p[j] = bk[i + j];
#pragma unroll
        for (int j = 0; j < 8; j++) if (j < m) v[j] = x2[(p[j] & 0x1FFFFu) * 32 + lane];
#pragma unroll
        for (int j = 0; j < 8; j++) if (j < m) {
            if (p[j] >> 17) { a1.x += v[j].x; a1.y += v[j].y; }
            else            { a0.x += v[j].x; a0.y += v[j].y; }
        }
    }

    int c1 = tot - c0;
    float inv0 = 1.f / (float)max(c0, 1);
    float inv1 = 1.f / (float)max(c1, 1);
    ((float2*)&g_Av[0][node * 16])[lane] = make_float2(a0.x * inv0, a0.y * inv0);
    ((float2*)&g_Av[1][node * 16])[lane] = make_float2(a1.x * inv1, a1.y * inv1);
}

// ---------------- feat: WMMA bf16x3 GEMM, BK=32, cp.async 3-stage fp32 A ring ----------------
// dynamic smem (bytes):
//   S32 @ 0      : 3 stages x [128][32] f32 = 49152
//   AH  @ 49152  : [2][128][40] bf16 = 20480
//   AL  @ 69632  : [2][128][40] bf16 = 20480
//   BH  @ 90112  : [2][32][72]  bf16 = 9216
//   BL  @ 99328  : [2][32][72]  bf16 = 9216
//   D   @ 0      : [128][68] f32 = 34816  (overlaps stage ring; used after last MMA)
//   TAB @ 108544 : 896 floats = 3584
#define ALD 40
#define BLD 72
#define DLD 68
#define F_OFF_S32 0u
#define F_OFF_AH  49152u
#define F_OFF_AL  69632u
#define F_OFF_BH  90112u
#define F_OFF_BL  99328u
#define F_OFF_TAB 108544u
#define F_SMEM_TOTAL (108544 + 3584)

__global__ __launch_bounds__(256) void feat_kernel(const float* __restrict__ des,
                                                   const float* __restrict__ num,
                                                   const float* __restrict__ cat)
{
    extern __shared__ __align__(128) char sm[];
    uint32_t smb = smem_u32(sm);
    __nv_bfloat16* AH = (__nv_bfloat16*)(sm + F_OFF_AH);
    __nv_bfloat16* AL = (__nv_bfloat16*)(sm + F_OFF_AL);
    __nv_bfloat16* BH = (__nv_bfloat16*)(sm + F_OFF_BH);
    __nv_bfloat16* BL = (__nv_bfloat16*)(sm + F_OFF_BL);
    float* Df  = (float*)(sm + F_OFF_S32);
    float* tab = (float*)(sm + F_OFF_TAB);

    int tid = threadIdx.x;
    int warp = tid >> 5;
    int wr = warp >> 1;
    int wc = warp & 1;
    int row0 = blockIdx.x * 128;

    // thread's A geometry: 4 x 16B slots; row = slot>>3, q = slot&7
    int arow[4], aq[4];
#pragma unroll
    for (int i = 0; i < 4; i++) {
        int u = tid + 256 * i;
        arow[i] = u >> 3;
        aq[i] = u & 7;
    }

    for (int i = tid; i < 896; i += 256) {
        float v;
        if (i < 64) v = g_bdes[i];
        else if (i < 128) v = g_bnum[i - 64];
        else if (i < 192) v = g_bcat[i - 128];
        else if (i < 512) v = g_Wnum[i - 192];
        else v = g_Wcat[i - 512];
        tab[i] = v;
    }

    wmma::fragment<wmma::accumulator, 16, 16, 16, float> acc[2][2];
#pragma unroll
    for (int i = 0; i < 2; i++)
#pragma unroll
        for (int j = 0; j < 2; j++) wmma::fill_fragment(acc[i][j], 0.f);

    uint2 fBh[2], fBl[2];

    auto issueA = [&](int t) {
        int kk = t * 32;
        uint32_t sbase = smb + F_OFF_S32 + (t % 3) * 16384;
#pragma unroll
        for (int i = 0; i < 4; i++) {
            int grow = row0 + arow[i];
            int srow = min(grow, NN - 1);          // clamp addr; size=0 zero-fills OOB rows
            const float* src = &des[(size_t)srow * KDES + kk + aq[i] * 4];
            cp16(sbase + arow[i] * 128 + aq[i] * 16, src, (grow < NN) ? 16 : 0);
        }
        cp_commit();
    };
    auto gloadB = [&](int t) {
#pragma unroll
        for (int s = 0; s < 2; s++) {
            int i4 = (tid + 256 * s) * 4;
            int r = i4 >> 6, c = i4 & 63;
            fBh[s] = *(const uint2*)&g_Bh[(t * 32 + r) * HH + c];
            fBl[s] = *(const uint2*)&g_Bl[(t * 32 + r) * HH + c];
        }
    };
    auto convertA = [&](int t, int b) {
        const char* S = sm + F_OFF_S32 + (t % 3) * 16384;
#pragma unroll
        for (int i = 0; i < 4; i++) {
            float4 f = *(const float4*)(S + arow[i] * 128 + aq[i] * 16);
            uint32_t h0 = bfpack(f.x, f.y);
            uint32_t h1 = bfpack(f.z, f.w);
            uint32_t l0 = bfpack(f.x - __uint_as_float(h0 << 16),
                                 f.y - __uint_as_float(h0 & 0xffff0000u));
            uint32_t l1 = bfpack(f.z - __uint_as_float(h1 << 16),
                                 f.w - __uint_as_float(h1 & 0xffff0000u));
            int eoff = (b * 128 + arow[i]) * ALD + aq[i] * 4;
            *(uint2*)&AH[eoff] = make_uint2(h0, h1);
            *(uint2*)&AL[eoff] = make_uint2(l0, l1);
        }
    };
    auto sstoreB = [&](int b) {
#pragma unroll
        for (int s = 0; s < 2; s++) {
            int i4 = (tid + 256 * s) * 4;
            int r = i4 >> 6, c = i4 & 63;
            int eoff = (b * 32 + r) * BLD + c;
            *(uint2*)&BH[eoff] = fBh[s];
            *(uint2*)&BL[eoff] = fBl[s];
        }
    };
    auto domma = [&](int b) {
#pragma unroll
        for (int kc = 0; kc < 2; kc++) {
            wmma::fragment<wmma::matrix_a, 16, 16, 16, __nv_bfloat16, wmma::row_major> ah[2], al[2];
            wmma::fragment<wmma::matrix_b, 16, 16, 16, __nv_bfloat16, wmma::row_major> bh[2], bl[2];
#pragma unroll
            for (int i = 0; i < 2; i++) {
                int base = (b * 128 + wr * 32 + i * 16) * ALD + kc * 16;
                wmma::load_matrix_sync(ah[i], AH + base, ALD);
                wmma::load_matrix_sync(al[i], AL + base, ALD);
            }
#pragma unroll
            for (int j = 0; j < 2; j++) {
                int base = (b * 32 + kc * 16) * BLD + wc * 32 + j * 16;
                wmma::load_matrix_sync(bh[j], BH + base, BLD);
                wmma::load_matrix_sync(bl[j], BL + base, BLD);
            }
#pragma unroll
            for (int i = 0; i < 2; i++)
#pragma unroll
                for (int j = 0; j < 2; j++) {
                    wmma::mma_sync(acc[i][j], ah[i], bh[j], acc[i][j]);
                    wmma::mma_sync(acc[i][j], ah[i], bl[j], acc[i][j]);
                    wmma::mma_sync(acc[i][j], al[i], bh[j], acc[i][j]);
                }
        }
    };

    const int T = KDES / 32;   // 24
    issueA(0); issueA(1); issueA(2);
    gloadB(0);

    for (int t = 0; t < T; t++) {
        int b = t & 1;
        if (t < T - 2)      cp_wait<2>();
        else if (t == T - 2) cp_wait<1>();
        else                 cp_wait<0>();
        __syncthreads();                 // stage t visible to all threads
        convertA(t, b);
        sstoreB(b);
        __syncthreads();                 // AH/AL/B[b] ready; stage buffer free
        if (t + 3 < T) issueA(t + 3);
        if (t + 1 < T) gloadB(t + 1);
        domma(b);
    }
    __syncthreads();

#pragma unroll
    for (int i = 0; i < 2; i++)
#pragma unroll
        for (int j = 0; j < 2; j++)
            wmma::store_matrix_sync(Df + (wr * 32 + i * 16) * DLD + wc * 32 + j * 16,
                                    acc[i][j], DLD, wmma::mem_row_major);
    __syncthreads();

    {
        int row = tid >> 1;
        int ch = (tid & 1) * 8;
        int grow = row0 + row;
        if (grow < NN) {
            float nb[5], cb[6];
#pragma unroll
            for (int j = 0; j < 5; j++) nb[j] = num[grow * 5 + j];
#pragma unroll
            for (int j = 0; j < 6; j++) cb[j] = cat[grow * 6 + j];
            const float4* bd4 = (const float4*)tab;
            const float4* bn4 = (const float4*)(tab + 64);
            const float4* bc4 = (const float4*)(tab + 128);
#pragma unroll
            for (int cq = 0; cq < 8; cq++) {
                int cqq = ch + cq;
                float4 d = *(const float4*)&Df[row * DLD + cqq * 4];
                float4 bd = bd4[cqq];
                float4 bn = bn4[cqq];
                float4 bc = bc4[cqq];
                float vn[4] = {bn.x, bn.y, bn.z, bn.w};
                float vc[4] = {bc.x, bc.y, bc.z, bc.w};
#pragma unroll
                for (int j = 0; j < 5; j++) {
                    float4 w = ((const float4*)(tab + 192 + j * 64))[cqq];
                    vn[0] += nb[j] * w.x; vn[1] += nb[j] * w.y;
                    vn[2] += nb[j] * w.z; vn[3] += nb[j] * w.w;
                }
#pragma unroll
                for (int j = 0; j < 6; j++) {
                    float4 w = ((const float4*)(tab + 512 + j * 64))[cqq];
                    vc[0] += cb[j] * w.x; vc[1] += cb[j] * w.y;
                    vc[2] += cb[j] * w.z; vc[3] += cb[j] * w.w;
                }
                float4 res;
                res.x = leaky(d.x + bd.x) + leaky(vn[0]) + leaky(vc[0]);
                res.y = leaky(d.y + bd.y) + leaky(vn[1]) + leaky(vc[1]);
                res.z = leaky(d.z + bd.z) + leaky(vn[2]) + leaky(vc[2]);
                res.w = leaky(d.w + bd.w) + leaky(vn[3]) + leaky(vc[3]);
                g_xv[grow * 16 + cqq] = res;
            }
        }
    }
}

// ---------------- finalA: Z = leaky(([M0;M1] @ [W0;W1]) * 0.5), K=128, single acc ----------------
__global__ __launch_bounds__(256) void finalA_kernel()
{
    __shared__ float As[2][16][132];
    __shared__ float Bs[2][16][64];
    int tid = threadIdx.x;
    int tx = tid & 15;
    int ty = tid >> 4;
    int row0 = blockIdx.x * 128;
    int c0 = tx * 4;
    int rl = ty * 8;

    int r0 = tid >> 2, kq0 = tid & 3;
    int r1 = (tid + 256) >> 2;
    int kb = tid >> 4, cb = (tid & 15) * 4;

    ull acc[4][4];
#pragma unroll
    for (int j = 0; j < 4; j++)
#pragma unroll
        for (int i = 0; i < 4; i++) acc[j][i] = 0ull;

    const float* Wflat = (const float*)g_Wr;

    float4 pA0, pA1, pB;
    auto gload = [&](int kk) {
        int kcat = kk + kq0 * 4;
        int rel = kcat >> 6;
        int offq = (kcat & 63) >> 2;
        int g0 = row0 + r0, g1 = row0 + r1;
        pA0 = (g0 < NN) ? g_Av[rel][g0 * 16 + offq] : make_float4(0.f, 0.f, 0.f, 0.f);
        pA1 = (g1 < NN) ? g_Av[rel][g1 * 16 + offq] : make_float4(0.f, 0.f, 0.f, 0.f);
        pB = *(const float4*)&Wflat[(kk + kb) * HH + cb];
    };
    auto sstore = [&](int buf) {
        As[buf][kq0 * 4 + 0][r0] = pA0.x;
        As[buf][kq0 * 4 + 1][r0] = pA0.y;
        As[buf][kq0 * 4 + 2][r0] = pA0.z;
        As[buf][kq0 * 4 + 3][r0] = pA0.w;
        As[buf][kq0 * 4 + 0][r1] = pA1.x;
        As[buf][kq0 * 4 + 1][r1] = pA1.y;
        As[buf][kq0 * 4 + 2][r1] = pA1.z;
        As[buf][kq0 * 4 + 3][r1] = pA1.w;
        *(float4*)&Bs[buf][kb][cb] = pB;
    };

    gload(0);
    sstore(0);
    __syncthreads();

#pragma unroll
    for (int t = 0; t < 8; t++) {
        int buf = t & 1;
        if (t + 1 < 8) gload((t + 1) * 16);
#pragma unroll
        for (int k = 0; k < 16; k++) {
            float4 b4 = *(const float4*)&Bs[buf][k][c0];
            ull bd0 = dupf(b4.x), bd1 = dupf(b4.y), bd2 = dupf(b4.z), bd3 = dupf(b4.w);
            ulonglong2 a01 = *(const ulonglong2*)&As[buf][k][rl];
            ulonglong2 a23 = *(const ulonglong2*)&As[buf][k][rl + 4];
            fma2(acc[0][0], a01.x, bd0); fma2(acc[0][1], a01.x, bd1);
            fma2(acc[0][2], a01.x, bd2); fma2(acc[0][3], a01.x, bd3);
            fma2(acc[1][0], a01.y, bd0); fma2(acc[1][1], a01.y, bd1);
            fma2(acc[1][2], a01.y, bd2); fma2(acc[1][3], a01.y, bd3);
            fma2(acc[2][0], a23.x, bd0); fma2(acc[2][1], a23.x, bd1);
            fma2(acc[2][2], a23.x, bd2); fma2(acc[2][3], a23.x, bd3);
            fma2(acc[3][0], a23.y, bd0); fma2(acc[3][1], a23.y, bd1);
            fma2(acc[3][2], a23.y, bd2); fma2(acc[3][3], a23.y, bd3);
        }
        if (t + 1 < 8) sstore((t + 1) & 1);
        __syncthreads();
    }

#pragma unroll
    for (int j = 0; j < 8; j++) {
        int grow = row0 + rl + j;
        if (grow < NN) {
            int jp = j >> 1, hi = j & 1;
            float res[4];
#pragma unroll
            for (int i = 0; i < 4; i++) {
                float2 u = unpk(acc[jp][i]);
                float v = hi ? u.y : u.x;
                res[i] = leaky(v * 0.5f);
            }
            g_xv[grow * 16 + tx] = make_float4(res[0], res[1], res[2], res[3]);
        }
    }
}

// ---------------- finalB: classifier, one thread per node ----------------
__global__ __launch_bounds__(256) void finalB_kernel(const float* __restrict__ W1,
                                                     const float* __restrict__ b1,
                                                     const float* __restrict__ W2,
                                                     const float* __restrict__ b2,
                                                     float* __restrict__ out)
{
    __shared__ ull   C1p[64][16];
    __shared__ float C2s[64];
    __shared__ float B1s[32];

    int tid = threadIdx.x;
    for (int idx = tid; idx < 1024; idx += 256) {
        int k = idx >> 4, p = idx & 15;
        C1p[k][p] = pk2(W1[(2 * p) * 64 + k], W1[(2 * p + 1) * 64 + k]);
    }
    if (tid < 64) C2s[tid] = W2[tid];
    if (tid < 32) B1s[tid] = b1[tid];
    __syncthreads();

    int n = blockIdx.x * 256 + tid;
    if (n >= NN) return;

    ull hacc[16];
#pragma unroll
    for (int p = 0; p < 16; p++) hacc[p] = 0ull;

    for (int kq = 0; kq < 16; kq++) {
        float4 z4 = g_xv[n * 16 + kq];
        float zc[4] = {z4.x, z4.y, z4.z, z4.w};
#pragma unroll
        for (int c = 0; c < 4; c++) {
            int k = kq * 4 + c;
            ull zd = dupf(zc[c]);
            const ulonglong2* wv = (const ulonglong2*)&C1p[k][0];
#pragma unroll
            for (int p2 = 0; p2 < 8; p2++) {
                ulonglong2 w = wv[p2];
                fma2(hacc[2 * p2 + 0], zd, w.x);
                fma2(hacc[2 * p2 + 1], zd, w.y);
            }
        }
    }

    float q0 = 0.f, q1 = 0.f;
#pragma unroll
    for (int p = 0; p < 16; p++) {
        float2 u = unpk(hacc[p]);
        float h0 = leaky(u.x + B1s[2 * p]);
        float h1 = leaky(u.y + B1s[2 * p + 1]);
        q0 += h0 * C2s[2 * p] + h1 * C2s[2 * p + 1];
        q1 += h0 * C2s[32 + 2 * p] + h1 * C2s[32 + 2 * p + 1];
    }
    out[n * 2 + 0] = q0 + b2[0];
    out[n * 2 + 1] = q1 + b2[1];
}

// ---------------- launch ----------------
extern "C" void kernel_launch(void* const* d_in, const int* in_sizes, int n_in,
                              void* d_out, int out_size)
{
    const float* des     = (const float*)d_in[0];
    const float* num     = (const float*)d_in[1];
    const float* cat     = (const float*)d_in[2];
    const int*   ei      = (const int*)d_in[3];
    const int*   et      = (const int*)d_in[4];
    const float* desW    = (const float*)d_in[5];
    const float* desb    = (const float*)d_in[6];
    const float* numW    = (const float*)d_in[7];
    const float* numb    = (const float*)d_in[8];
    const float* catW    = (const float*)d_in[9];
    const float* catb    = (const float*)d_in[10];
    const float* desg    = (const float*)d_in[11];
    const float* desbeta = (const float*)d_in[12];
    const float* desm    = (const float*)d_in[13];
    const float* desv    = (const float*)d_in[14];
    const float* numg    = (const float*)d_in[15];
    const float* numbeta = (const float*)d_in[16];
    const float* numm    = (const float*)d_in[17];
    const float* numv    = (const float*)d_in[18];
    const float* catg    = (const float*)d_in[19];
    const float* catbeta = (const float*)d_in[20];
    const float* catm    = (const float*)d_in[21];
    const float* catv    = (const float*)d_in[22];
    const float* rgcnW   = (const float*)d_in[23];
    const float* clsW1   = (const float*)d_in[24];
    const float* clsb1   = (const float*)d_in[25];
    const float* clsW2   = (const float*)d_in[26];
    const float* clsb2   = (const float*)d_in[27];
    float* out = (float*)d_out;

    cudaFuncSetAttribute(feat_kernel, cudaFuncAttributeMaxDynamicSharedMemorySize,
                         F_SMEM_TOTAL);

    prep_kernel<<<(KDES * HH + 255) / 256, 256>>>(
        desW, desb, numW, numb, catW, catb,
        desg, desbeta, desm, desv,
        numg, numbeta, numm, numv,
        catg, catbeta, catm, catv,
        rgcnW);

    zero_kernel<<<(NN + 255) / 256, 256>>>();

    build_kernel<<<(EE + 255) / 256, 256>>>(ei, et);

    feat_kernel<<<(NN + 127) / 128, 256, F_SMEM_TOTAL>>>(des, num, cat);

    aggregate_kernel<<<(NN * 32 + 255) / 256, 256>>>();

    finalA_kernel<<<(NN + 127) / 128, 256>>>();

    finalB_kernel<<<(NN + 255) / 256, 256>>>(clsW1, clsb1, clsW2, clsb2, out);
}